// round 11
// baseline (speedup 1.0000x reference)
#include <cuda_runtime.h>
#include <math.h>
#include <cooperative_groups.h>
namespace cg = cooperative_groups;

#define Bb 16
#define Ss 256
#define Ee 256
#define ROWS (Bb*Ss)
#define FFNf 1024

typedef unsigned long long u64;

__device__ float g_zx [ROWS*1024];
__device__ float g_wxp[256*1024];
__device__ float g_bth[1024];
__device__ float g_h  [ROWS*Ee];
__device__ float g_q  [ROWS*Ee];
__device__ float g_k  [ROWS*Ee];
__device__ float g_v  [ROWS*Ee];
__device__ float g_at [ROWS*Ee];
__device__ float g_ffq[ROWS*Ee];
__device__ float g_t1 [ROWS*FFNf];
__device__ float g_t2 [ROWS*Ee];

__device__ __forceinline__ float sigm_f(float x) { return 1.f / (1.f + __expf(-x)); }
__device__ __forceinline__ float tanh_f(float x) {
    float t = __expf(-2.f * x);
    return (1.f - t) / (1.f + t);
}

// ---- packed fp32x2 helpers (sm_103a FFMA2) ----
__device__ __forceinline__ u64 pk2(float x) {
    u64 r; asm("mov.b64 %0, {%1, %1};" : "=l"(r) : "f"(x)); return r;
}
__device__ __forceinline__ void f2(u64& a, u64 x, u64 y) {
    asm("fma.rn.f32x2 %0, %1, %2, %0;" : "+l"(a) : "l"(x), "l"(y));
}
__device__ __forceinline__ void upk2(u64 v, float& lo, float& hi) {
    asm("mov.b64 {%0, %1}, %2;" : "=f"(lo), "=f"(hi) : "l"(v));
}
__device__ __forceinline__ uint32_t smem_u32(const void* p) {
    uint32_t a;
    asm("{ .reg .u64 t; cvta.to.shared.u64 t, %1; cvt.u32.u64 %0, t; }"
        : "=r"(a) : "l"(p));
    return a;
}
__device__ __forceinline__ void mbar_wait_cluster(uint32_t mbar, uint32_t ph) {
    asm volatile(
        "{\n\t.reg .pred P;\n"
        "LW_%=:\n\t"
        "mbarrier.try_wait.parity.acquire.cluster.shared::cta.b64 P, [%0], %1, 0x989680;\n\t"
        "@P bra.uni LD_%=;\n\t"
        "bra.uni LW_%=;\n"
        "LD_%=:\n\t}"
        :: "r"(mbar), "r"(ph) : "memory");
}

// pack Wx -> [k][g*256+j]
__global__ void pack_w_kernel(const float* __restrict__ W) {
    int idx = blockIdx.x * 256 + threadIdx.x;
    int k = idx >> 10, n = idx & 1023, g = n >> 8, j = n & 255;
    g_wxp[idx] = W[g * 131072 + k * 256 + j];
}
// fold b+theta
__global__ void pack_b_kernel(const float* __restrict__ B, const float* __restrict__ Th) {
    int idx = blockIdx.x * 256 + threadIdx.x;
    g_bth[idx] = B[idx] + Th[idx];
}

// ---- fp32 GEMM (round-8 proven config): 128xTN tile, 256 thr, 8x(TN/16) micro ----
template<int TN, bool GATHER, bool RELU>
__global__ __launch_bounds__(256) void gemm_kernel(
    const float* __restrict__ A, const float* __restrict__ Bm, float* __restrict__ C,
    int M, int N, int K, const float* __restrict__ bias,
    const int* __restrict__ tok, const float* __restrict__ emb)
{
    constexpr int NW = TN / 16;   // 8 or 4
    constexpr int NP = NW / 2;
    __shared__ float AsT[2][16][136];
    __shared__ float Bs [2][16][136];
    __shared__ int   toks[128];
    const int t = threadIdx.x;
    const int n0 = blockIdx.x * TN, m0 = blockIdx.y << 7;
    const int ar = t >> 1, ac8 = (t & 1) << 3;
    const int bk = t >> 4;
    const int bn = (TN == 128) ? ((t & 15) << 3) : ((t & 15) << 2);
    const int tyo = (t >> 4) << 3, txo = (t & 15) * NW;
    if (GATHER) { if (t < 128) toks[t] = tok[m0 + t]; __syncthreads(); }
    const float* arow = GATHER ? (emb + (size_t)toks[ar] * K)
                               : (A   + (size_t)(m0 + ar) * K);
    const float* brow = Bm + (size_t)bk * N + n0 + bn;

    u64 acc[8][NP];
#pragma unroll
    for (int i = 0; i < 8; i++)
#pragma unroll
        for (int j = 0; j < NP; j++) acc[i][j] = 0ull;

    float4 av0 = *(const float4*)(arow + ac8);
    float4 av1 = *(const float4*)(arow + ac8 + 4);
    float4 bv0 = *(const float4*)(brow);
    float4 bv1;
    if (TN == 128) bv1 = *(const float4*)(brow + 4);

    int s = 0, k0 = 0;
    while (true) {
        AsT[s][ac8+0][ar]=av0.x; AsT[s][ac8+1][ar]=av0.y;
        AsT[s][ac8+2][ar]=av0.z; AsT[s][ac8+3][ar]=av0.w;
        AsT[s][ac8+4][ar]=av1.x; AsT[s][ac8+5][ar]=av1.y;
        AsT[s][ac8+6][ar]=av1.z; AsT[s][ac8+7][ar]=av1.w;
        *(float4*)(&Bs[s][bk][bn]) = bv0;
        if (TN == 128) *(float4*)(&Bs[s][bk][bn+4]) = bv1;
        __syncthreads();
        k0 += 16;
        const bool more = (k0 < K);
        if (more) {
            av0 = *(const float4*)(arow + k0 + ac8);
            av1 = *(const float4*)(arow + k0 + ac8 + 4);
            bv0 = *(const float4*)(brow + (size_t)k0 * N);
            if (TN == 128) bv1 = *(const float4*)(brow + (size_t)k0 * N + 4);
        }
#pragma unroll
        for (int kk = 0; kk < 16; kk++) {
            float4 af0 = *(const float4*)(&AsT[s][kk][tyo]);
            float4 af1 = *(const float4*)(&AsT[s][kk][tyo + 4]);
            u64 a2[8];
            a2[0]=pk2(af0.x); a2[1]=pk2(af0.y); a2[2]=pk2(af0.z); a2[3]=pk2(af0.w);
            a2[4]=pk2(af1.x); a2[5]=pk2(af1.y); a2[6]=pk2(af1.z); a2[7]=pk2(af1.w);
            u64 bp[NP];
            {
                ulonglong2 bb0 = *(const ulonglong2*)(&Bs[s][kk][txo]);
                bp[0] = bb0.x; bp[1] = bb0.y;
                if (TN == 128) {
                    ulonglong2 bb1 = *(const ulonglong2*)(&Bs[s][kk][txo + 4]);
                    bp[2] = bb1.x; bp[3] = bb1.y;
                }
            }
#pragma unroll
            for (int i = 0; i < 8; i++)
#pragma unroll
                for (int j = 0; j < NP; j++) f2(acc[i][j], a2[i], bp[j]);
        }
        if (!more) break;
        s ^= 1;
    }
    float bb[NW];
#pragma unroll
    for (int j = 0; j < NW; j++) bb[j] = bias[n0 + txo + j];
#pragma unroll
    for (int i = 0; i < 8; i++) {
        float ov[NW];
#pragma unroll
        for (int j = 0; j < NP; j++) {
            float lo, hi;
            upk2(acc[i][j], lo, hi);
            ov[2*j]   = lo + bb[2*j];
            ov[2*j+1] = hi + bb[2*j+1];
        }
        if (RELU) {
#pragma unroll
            for (int j = 0; j < NW; j++) ov[j] = fmaxf(ov[j], 0.f);
        }
        float* cp = C + (size_t)(m0 + tyo + i) * N + n0 + txo;
        *(float4*)cp = make_float4(ov[0], ov[1], ov[2], ov[3]);
        if (TN == 128) *(float4*)(cp + 4) = make_float4(ov[4], ov[5], ov[6], ov[7]);
    }
}

// ---------------------------------------------------------------------------
// QLSTM recurrence: cluster of 8, W in registers.
// Gate exchange: plain st.shared::cluster stores + fence.acq_rel.cluster +
// ONE mbarrier.arrive per source CTA (count=8) — removes the per-element
// mbarrier transaction serialization that dominated the st.async version.
// ---------------------------------------------------------------------------
#define LSTM_SMEM_FLOATS (8*132 + 2*8*132 + 256 + 256 + 8 + 8)
__global__ __cluster_dims__(8,1,1) __launch_bounds__(256)
void lstm_kernel(const float* __restrict__ W, float* __restrict__ hseq)
{
    extern __shared__ float sm[];
    float* red  = sm;                          // [8][132]
    float* allq = red + 8*132;                 // [2][8][132]
    float* hx   = allq + 2*8*132;              // [256]
    float* cx   = hx + 256;                    // [256]
    float* wtot = cx + 256;                    // [8]
    u64*   mbar = (u64*)(wtot + 8);            // [2]

    cg::cluster_group cluster = cg::this_cluster();
    const int rank = (int)cluster.block_rank();
    const int g    = rank >> 1, half = rank & 1;
    const int b    = blockIdx.x >> 3;
    const int t    = threadIdx.x;
    const int ks   = t >> 5, jc = t & 31;
    const int lane = t & 31, w = t >> 5;

    const uint32_t allq32 = smem_u32(allq);
    const uint32_t mbar32 = smem_u32(mbar);

    if (t == 0) {   // 8 arrivals per phase: one per source CTA
        asm volatile("mbarrier.init.shared.b64 [%0], 8;" :: "r"(mbar32) : "memory");
        asm volatile("mbarrier.init.shared.b64 [%0], 8;" :: "r"(mbar32 + 8) : "memory");
    }

    const float* gW = W + g * 131072 + 65536 + half * 128;
    ulonglong2 wr[32];
#pragma unroll
    for (int kk = 0; kk < 32; kk++)
        wr[kk] = *(const ulonglong2*)(gW + (size_t)((kk << 3) + ks) * 256 + (jc << 2));

    hx[t] = 0.f; cx[t] = 0.f;

    float pediv = __expf((float)((t >> 1) << 1) * (-9.210340371976184f / 256.f));

    uint32_t paq[8], pmb[8];
#pragma unroll
    for (int r = 0; r < 8; r++) {
        asm("mapa.shared::cluster.u32 %0, %1, %2;" : "=r"(paq[r]) : "r"(allq32), "r"(r));
        asm("mapa.shared::cluster.u32 %0, %1, %2;" : "=r"(pmb[r]) : "r"(mbar32), "r"(r));
    }

    __syncthreads();
    cluster.sync();   // barriers visible before any store/arrive

    const float* zxp = g_zx + (size_t)b * 256 * 1024 + g * 256 + half * 128;
    float zcur = (t < 128) ? zxp[t] : 0.f;

    for (int step = 0; step < 256; ++step) {
        const int par = step & 1;
        // ---- dot: hx @ Wslice, all from registers ----
        u64 acc01 = 0ull, acc23 = 0ull;
#pragma unroll
        for (int kk = 0; kk < 32; ++kk) {
            u64 hv2 = pk2(hx[(kk << 3) + ks]);
            f2(acc01, hv2, wr[kk].x);
            f2(acc23, hv2, wr[kk].y);
        }
        float znext = 0.f;
        if (t < 128) {
            int sn = (step < 255) ? step + 1 : step;
            znext = zxp[(size_t)sn * 1024 + t];
        }
        {
            float a0, a1, a2, a3;
            upk2(acc01, a0, a1); upk2(acc23, a2, a3);
            *(float4*)&red[ks * 132 + (jc << 2)] = make_float4(a0, a1, a2, a3);
        }
        __syncthreads();
        // ---- z, cos, local cumprod over 128 cols ----
        float p = 0.f;
        if (t < 128) {
            float z = red[t] + red[132 + t] + red[264 + t] + red[396 + t]
                    + red[528 + t] + red[660 + t] + red[792 + t] + red[924 + t]
                    + zcur;
            p = __cosf(z);
#pragma unroll
            for (int off = 1; off < 32; off <<= 1) {
                float u = __shfl_up_sync(0xffffffffu, p, off);
                if (lane >= off) p *= u;
            }
            if (lane == 31) wtot[w] = p;
        }
        zcur = znext;
        __syncthreads();
        // ---- push scanned slice to all peers (plain DSMEM stores) ----
        if (t < 128) {
            float pre = 1.f;
            for (int ww = 0; ww < w; ++ww) pre *= wtot[ww];
            float sv = p * pre;
            const uint32_t off4 = (uint32_t)(par * 1056 + rank * 132 + t) * 4u;
            const uint32_t svb = __float_as_uint(sv);
#pragma unroll
            for (int r = 0; r < 8; r++) {
                asm volatile("st.shared::cluster.u32 [%0], %1;"
                             :: "r"(paq[r] + off4), "r"(svb) : "memory");
            }
            asm volatile("fence.acq_rel.cluster;" ::: "memory");
        }
        __syncthreads();
        if (t == 0) {   // single release-arrive per peer barrier
#pragma unroll
            for (int r = 0; r < 8; r++) {
                asm volatile(
                    "mbarrier.arrive.release.cluster.shared::cluster.b64 _, [%0];"
                    :: "r"(pmb[r] + par * 8) : "memory");
            }
        }
        mbar_wait_cluster(mbar32 + par * 8, (uint32_t)((step >> 1) & 1));
        // ---- gates from LOCAL allq + state update (replicated) ----
        {
            const int sh = t >> 7, off = t & 127;
            const float* aq = allq + par * 1056;
            float qg4[4];
#pragma unroll
            for (int gg = 0; gg < 4; gg++) {
                float v = aq[(gg * 2 + sh) * 132 + off];
                if (sh) v *= aq[(gg * 2) * 132 + 127];
                qg4[gg] = v;
            }
            float f  = sigm_f(qg4[0]);
            float ii = sigm_f(qg4[1]);
            float gg = tanh_f(qg4[2]);
            float oo = sigm_f(qg4[3]);
            float cn = f * cx[t] + ii * gg;
            cx[t] = cn;
            float hn = oo * tanh_f(cn);
            hx[t] = hn;
            if (rank == 0) {
                float ang = (float)step * pediv;
                float pe  = (t & 1) ? __cosf(ang) : __sinf(ang);
                hseq[((size_t)b * 256 + step) * 256 + t] = hn + pe;
            }
        }
        __syncthreads();
    }
    cluster.sync();
}

// fused q/k/v qproj: one warp per row, reads h once, writes 3 outputs
__global__ void qproj3_kernel(const float* __restrict__ h, const float* __restrict__ th,
                              float* __restrict__ qo, float* __restrict__ ko,
                              float* __restrict__ vo) {
    const int w = threadIdx.x >> 5, lane = threadIdx.x & 31;
    const int row = blockIdx.x * 8 + w;
    const float* hr = h + (size_t)row * 256 + lane * 8;
    float4 h0 = *(const float4*)hr, h1 = *(const float4*)(hr + 4);
    float* outs[3] = {qo, ko, vo};
#pragma unroll
    for (int c = 0; c < 3; c++) {
        const float* tr = th + c * 256 + lane * 8;
        float4 t0 = *(const float4*)tr, t1 = *(const float4*)(tr + 4);
        float p[8], run;
        run  = __cosf(h0.x+t0.x); p[0]=run;  run *= __cosf(h0.y+t0.y); p[1]=run;
        run *= __cosf(h0.z+t0.z); p[2]=run;  run *= __cosf(h0.w+t0.w); p[3]=run;
        run *= __cosf(h1.x+t1.x); p[4]=run;  run *= __cosf(h1.y+t1.y); p[5]=run;
        run *= __cosf(h1.z+t1.z); p[6]=run;  run *= __cosf(h1.w+t1.w); p[7]=run;
        float incl = run;
#pragma unroll
        for (int off = 1; off < 32; off <<= 1) {
            float u = __shfl_up_sync(0xffffffffu, incl, off);
            if (lane >= off) incl *= u;
        }
        float ex = __shfl_up_sync(0xffffffffu, incl, 1);
        if (lane == 0) ex = 1.f;
        float* o = outs[c] + (size_t)row * 256 + lane * 8;
        *(float4*)o     = make_float4(ex*p[0], ex*p[1], ex*p[2], ex*p[3]);
        *(float4*)(o+4) = make_float4(ex*p[4], ex*p[5], ex*p[6], ex*p[7]);
    }
}

// fused attention, 2-row blocking per warp, FFMA2 inner products
#define ATTN_SMEM (36864 + 33280 + 16384 + 2048)
__global__ __launch_bounds__(256) void attn_kernel(const float* __restrict__ Q,
    const float* __restrict__ K, const float* __restrict__ V, float* __restrict__ O)
{
    extern __shared__ float sm[];
    float* kh = sm;               // [256][36]
    float* vt = sm + 256 * 36;    // [32][260]
    float* ps = vt + 32 * 260;    // [8][2][256]
    float* qs = ps + 8 * 512;     // [8][64]
    const int b = blockIdx.x >> 3, hh = blockIdx.x & 7;
    const int t = threadIdx.x, w = t >> 5, lane = t & 31;
    const size_t base = ((size_t)b * 256) * 256 + hh * 32;
    for (int idx = t; idx < 8192; idx += 256) {
        int kr = idx >> 5, d = idx & 31;
        size_t go = base + (size_t)kr * 256 + d;
        kh[kr * 36 + d]  = K[go];
        vt[d * 260 + kr] = V[go];
    }
    __syncthreads();
    float* qsw = qs + w * 64;
    float* ps0 = ps + w * 512;
    float* ps1 = ps0 + 256;
    for (int i = 0; i < 16; i++) {
        const int r0 = w + 8 * i, r1 = r0 + 128;
        qsw[lane]      = Q[base + (size_t)r0 * 256 + lane];
        qsw[32 + lane] = Q[base + (size_t)r1 * 256 + lane];
        __syncwarp();
        u64 qa[16], qb[16];
        {
            const ulonglong2* qp = (const ulonglong2*)qsw;
#pragma unroll
            for (int u = 0; u < 8; u++) {
                ulonglong2 v0 = qp[u];     qa[2*u] = v0.x; qa[2*u+1] = v0.y;
                ulonglong2 v1 = qp[u + 8]; qb[2*u] = v1.x; qb[2*u+1] = v1.y;
            }
        }
        float s0[8], s1[8];
#pragma unroll
        for (int c = 0; c < 8; c++) {
            const ulonglong2* kp = (const ulonglong2*)(kh + (c * 32 + lane) * 36);
            u64 a0 = 0ull, a1 = 0ull;
#pragma unroll
            for (int u = 0; u < 8; u++) {
                ulonglong2 kv = kp[u];
                f2(a0, qa[2*u], kv.x); f2(a0, qa[2*u+1], kv.y);
                f2(a1, qb[2*u], kv.x); f2(a1, qb[2*u+1], kv.y);
            }
            float lo, hi;
            upk2(a0, lo, hi); s0[c] = (lo + hi) * 0.17677669529663689f;
            upk2(a1, lo, hi); s1[c] = (lo + hi) * 0.17677669529663689f;
        }
        float m0 = s0[0], m1 = s1[0];
#pragma unroll
        for (int c = 1; c < 8; c++) { m0 = fmaxf(m0, s0[c]); m1 = fmaxf(m1, s1[c]); }
#pragma unroll
        for (int off = 16; off; off >>= 1) {
            m0 = fmaxf(m0, __shfl_xor_sync(0xffffffffu, m0, off));
            m1 = fmaxf(m1, __shfl_xor_sync(0xffffffffu, m1, off));
        }
        float sum0 = 0.f, sum1 = 0.f;
#pragma unroll
        for (int c = 0; c < 8; c++) {
            s0[c] = __expf(s0[c] - m0); sum0 += s0[c];
            s1[c] = __expf(s1[c] - m1); sum1 += s1[c];
        }
#pragma unroll
        for (int off = 16; off; off >>= 1) {
            sum0 += __shfl_xor_sync(0xffffffffu, sum0, off);
            sum1 += __shfl_xor_sync(0xffffffffu, sum1, off);
        }
#pragma unroll
        for (int c = 0; c < 8; c++) {
            ps0[c * 32 + lane] = s0[c];
            ps1[c * 32 + lane] = s1[c];
        }
        __syncwarp();
        u64 a0 = 0ull, a1 = 0ull;
        const ulonglong2* pp0 = (const ulonglong2*)ps0;
        const ulonglong2* pp1 = (const ulonglong2*)ps1;
        const ulonglong2* vp  = (const ulonglong2*)(vt + lane * 260);
#pragma unroll
        for (int k8 = 0; k8 < 64; k8++) {
            ulonglong2 vv = vp[k8];
            ulonglong2 p0 = pp0[k8];
            ulonglong2 p1 = pp1[k8];
            f2(a0, p0.x, vv.x); f2(a0, p0.y, vv.y);
            f2(a1, p1.x, vv.x); f2(a1, p1.y, vv.y);
        }
        float lo, hi;
        upk2(a0, lo, hi); O[base + (size_t)r0 * 256 + lane] = (lo + hi) / sum0;
        upk2(a1, lo, hi); O[base + (size_t)r1 * 256 + lane] = (lo + hi) / sum1;
        __syncwarp();
    }
}

// residual add + LayerNorm; optionally fused qproj of the LN output (NQ outputs)
template<int NQ>
__global__ void resid_ln_kernel(float* __restrict__ h, const float* __restrict__ d,
                                const float* __restrict__ gw, const float* __restrict__ bw,
                                const float* __restrict__ th,
                                float* __restrict__ q0, float* __restrict__ q1,
                                float* __restrict__ q2) {
    const int row = blockIdx.x, j = threadIdx.x, w = j >> 5, lane = j & 31;
    __shared__ float ssum[8], ssq[8], wt[3][8];
    size_t off = (size_t)row * 256 + j;
    float v = h[off] + d[off];
    float s = v, s2 = v * v;
#pragma unroll
    for (int o = 16; o; o >>= 1) {
        s  += __shfl_xor_sync(0xffffffffu, s, o);
        s2 += __shfl_xor_sync(0xffffffffu, s2, o);
    }
    if (lane == 0) { ssum[w] = s; ssq[w] = s2; }
    __syncthreads();
    if (j == 0) {
        float S = 0.f, S2 = 0.f;
        for (int i = 0; i < 8; i++) { S += ssum[i]; S2 += ssq[i]; }
        ssum[0] = S; ssq[0] = S2;
    }
    __syncthreads();
    float mean = ssum[0] * (1.f/256.f);
    float var  = ssq[0]  * (1.f/256.f) - mean * mean;
    float nv = (v - mean) * rsqrtf(var + 1e-5f) * gw[j] + bw[j];
    h[off] = nv;
    if (NQ > 0) {
        float* outs[3] = {q0, q1, q2};
#pragma unroll
        for (int c = 0; c < NQ; c++) {
            float p = __cosf(nv + th[c * 256 + j]);
#pragma unroll
            for (int o = 1; o < 32; o <<= 1) {
                float u = __shfl_up_sync(0xffffffffu, p, o);
                if (lane >= o) p *= u;
            }
            if (lane == 31) wt[c][w] = p;
            __syncthreads();
            float pre = 1.f;
            for (int ww = 0; ww < w; ++ww) pre *= wt[c][ww];
            outs[c][off] = p * pre;
        }
    }
}

__global__ void pool_cls_kernel(const float* __restrict__ h, const float* __restrict__ Wc,
                                const float* __restrict__ bc, float* __restrict__ out) {
    __shared__ float pooled[256];
    const int b = blockIdx.x, e = threadIdx.x;
    float s = 0.f;
    for (int tt = 0; tt < 256; ++tt) s += h[((size_t)b * 256 + tt) * 256 + e];
    pooled[e] = s * (1.f/256.f);
    __syncthreads();
    if (e < 4) {
        float a = bc[e];
        for (int i = 0; i < 256; i++) a = fmaf(pooled[i], Wc[i * 4 + e], a);
        out[b * 4 + e] = a;
    }
}

extern "C" void kernel_launch(void* const* d_in, const int* in_sizes, int n_in,
                              void* d_out, int out_size)
{
    const int*   x      = (const int*)  d_in[0];
    const float* tokemb = (const float*)d_in[1];
    const float* lstmW  = (const float*)d_in[2];
    const float* lstmB  = (const float*)d_in[3];
    const float* lstmTh = (const float*)d_in[4];
    const float* ln1g   = (const float*)d_in[5];
    const float* ln1b   = (const float*)d_in[6];
    const float* ln2g   = (const float*)d_in[7];
    const float* ln2b   = (const float*)d_in[8];
    const float* qkvTh  = (const float*)d_in[9];
    const float* combW  = (const float*)d_in[10];
    const float* combB  = (const float*)d_in[11];
    const float* ffnTh  = (const float*)d_in[12];
    const float* lin1W  = (const float*)d_in[13];
    const float* lin1B  = (const float*)d_in[14];
    const float* lin2W  = (const float*)d_in[15];
    const float* lin2B  = (const float*)d_in[16];
    const float* clsW   = (const float*)d_in[17];
    const float* clsB   = (const float*)d_in[18];
    float* out = (float*)d_out;

    float *p_zx,*p_wxp,*p_bth,*p_h,*p_q,*p_k,*p_v,*p_at,*p_ffq,*p_t1,*p_t2;
    cudaGetSymbolAddress((void**)&p_zx,  g_zx);
    cudaGetSymbolAddress((void**)&p_wxp, g_wxp);
    cudaGetSymbolAddress((void**)&p_bth, g_bth);
    cudaGetSymbolAddress((void**)&p_h,   g_h);
    cudaGetSymbolAddress((void**)&p_q,   g_q);
    cudaGetSymbolAddress((void**)&p_k,   g_k);
    cudaGetSymbolAddress((void**)&p_v,   g_v);
    cudaGetSymbolAddress((void**)&p_at,  g_at);
    cudaGetSymbolAddress((void**)&p_ffq, g_ffq);
    cudaGetSymbolAddress((void**)&p_t1,  g_t1);
    cudaGetSymbolAddress((void**)&p_t2,  g_t2);

    cudaFuncSetAttribute(attn_kernel, cudaFuncAttributeMaxDynamicSharedMemorySize, ATTN_SMEM);
    cudaFuncSetAttribute(lstm_kernel, cudaFuncAttributeMaxDynamicSharedMemorySize,
                         LSTM_SMEM_FLOATS * 4);

    pack_w_kernel<<<1024, 256>>>(lstmW);
    pack_b_kernel<<<4, 256>>>(lstmB, lstmTh);
    // zx = gather(emb) @ Wx + (b+theta): round-8 proven config
    gemm_kernel<128, true, false><<<dim3(8, 32), 256>>>(
        nullptr, p_wxp, p_zx, ROWS, 1024, 256, p_bth, x, tokemb);
    lstm_kernel<<<128, 256, LSTM_SMEM_FLOATS * 4>>>(lstmW, p_h);

    // ---- layer 0 ----
    qproj3_kernel<<<ROWS/8, 256>>>(p_h, qkvTh, p_q, p_k, p_v);
    attn_kernel<<<Bb*8, 256, ATTN_SMEM>>>(p_q, p_k, p_v, p_at);
    gemm_kernel<64, false, false><<<dim3(4, 32), 256>>>(
        p_at, combW, p_t2, ROWS, 256, 256, combB, nullptr, nullptr);
    resid_ln_kernel<1><<<ROWS, 256>>>(p_h, p_t2, ln1g, ln1b, ffnTh,
                                      p_ffq, nullptr, nullptr);
    gemm_kernel<128, false, true><<<dim3(8, 32), 256>>>(
        p_ffq, lin1W, p_t1, ROWS, 1024, 256, lin1B, nullptr, nullptr);
    gemm_kernel<64, false, false><<<dim3(4, 32), 256>>>(
        p_t1, lin2W, p_t2, ROWS, 256, 1024, lin2B, nullptr, nullptr);
    resid_ln_kernel<3><<<ROWS, 256>>>(p_h, p_t2, ln2g, ln2b, qkvTh + 3*256,
                                      p_q, p_k, p_v);

    // ---- layer 1 ----
    attn_kernel<<<Bb*8, 256, ATTN_SMEM>>>(p_q, p_k, p_v, p_at);
    gemm_kernel<64, false, false><<<dim3(4, 32), 256>>>(
        p_at, combW + 256*256, p_t2, ROWS, 256, 256, combB + 256, nullptr, nullptr);
    resid_ln_kernel<1><<<ROWS, 256>>>(p_h, p_t2, ln1g + 256, ln1b + 256,
                                      ffnTh + 256, p_ffq, nullptr, nullptr);
    gemm_kernel<128, false, true><<<dim3(8, 32), 256>>>(
        p_ffq, lin1W + 256*1024, p_t1, ROWS, 1024, 256, lin1B + 1024,
        nullptr, nullptr);
    gemm_kernel<64, false, false><<<dim3(4, 32), 256>>>(
        p_t1, lin2W + 1024*256, p_t2, ROWS, 256, 1024, lin2B + 256,
        nullptr, nullptr);
    resid_ln_kernel<0><<<ROWS, 256>>>(p_h, p_t2, ln2g + 256, ln2b + 256,
                                      nullptr, nullptr, nullptr, nullptr);

    pool_cls_kernel<<<Bb, 256>>>(p_h, clsW, clsB, out);
}

// round 12
// speedup vs baseline: 1.8378x; 1.8378x over previous
#include <cuda_runtime.h>
#include <math.h>
#include <cooperative_groups.h>
namespace cg = cooperative_groups;

#define Bb 16
#define Ss 256
#define Ee 256
#define ROWS (Bb*Ss)
#define FFNf 1024

typedef unsigned long long u64;

__device__ float g_zx [ROWS*1024];
__device__ float g_wxp[256*1024];
__device__ float g_bth[1024];
__device__ float g_h  [ROWS*Ee];
__device__ float g_q  [ROWS*Ee];
__device__ float g_k  [ROWS*Ee];
__device__ float g_v  [ROWS*Ee];
__device__ float g_at [ROWS*Ee];
__device__ float g_ffq[ROWS*Ee];
__device__ float g_t1 [ROWS*FFNf];
__device__ float g_t2 [ROWS*Ee];

__device__ __forceinline__ float sigm_f(float x) { return 1.f / (1.f + __expf(-x)); }
__device__ __forceinline__ float tanh_f(float x) {
    float t = __expf(-2.f * x);
    return (1.f - t) / (1.f + t);
}

// ---- packed fp32x2 helpers (sm_103a FFMA2) ----
__device__ __forceinline__ u64 pk2(float x) {
    u64 r; asm("mov.b64 %0, {%1, %1};" : "=l"(r) : "f"(x)); return r;
}
__device__ __forceinline__ void f2(u64& a, u64 x, u64 y) {
    asm("fma.rn.f32x2 %0, %1, %2, %0;" : "+l"(a) : "l"(x), "l"(y));
}
__device__ __forceinline__ void upk2(u64 v, float& lo, float& hi) {
    asm("mov.b64 {%0, %1}, %2;" : "=f"(lo), "=f"(hi) : "l"(v));
}
__device__ __forceinline__ uint32_t smem_u32(const void* p) {
    uint32_t a;
    asm("{ .reg .u64 t; cvta.to.shared.u64 t, %1; cvt.u32.u64 %0, t; }"
        : "=r"(a) : "l"(p));
    return a;
}
__device__ __forceinline__ void mbar_wait_cluster(uint32_t mbar, uint32_t ph) {
    asm volatile(
        "{\n\t.reg .pred P;\n"
        "LW_%=:\n\t"
        "mbarrier.try_wait.parity.acquire.cluster.shared::cta.b64 P, [%0], %1, 0x989680;\n\t"
        "@P bra.uni LD_%=;\n\t"
        "bra.uni LW_%=;\n"
        "LD_%=:\n\t}"
        :: "r"(mbar), "r"(ph) : "memory");
}

// pack Wx -> [k][g*256+j]
__global__ void pack_w_kernel(const float* __restrict__ W) {
    int idx = blockIdx.x * 256 + threadIdx.x;
    int k = idx >> 10, n = idx & 1023, g = n >> 8, j = n & 255;
    g_wxp[idx] = W[g * 131072 + k * 256 + j];
}
// fold b+theta
__global__ void pack_b_kernel(const float* __restrict__ B, const float* __restrict__ Th) {
    int idx = blockIdx.x * 256 + threadIdx.x;
    g_bth[idx] = B[idx] + Th[idx];
}

// ---- fp32 GEMM (round-8 proven config): 128xTN tile, 256 thr, 8x(TN/16) micro ----
template<int TN, bool GATHER, bool RELU>
__global__ __launch_bounds__(256) void gemm_kernel(
    const float* __restrict__ A, const float* __restrict__ Bm, float* __restrict__ C,
    int M, int N, int K, const float* __restrict__ bias,
    const int* __restrict__ tok, const float* __restrict__ emb)
{
    constexpr int NW = TN / 16;   // 8 or 4
    constexpr int NP = NW / 2;
    __shared__ float AsT[2][16][136];
    __shared__ float Bs [2][16][136];
    __shared__ int   toks[128];
    const int t = threadIdx.x;
    const int n0 = blockIdx.x * TN, m0 = blockIdx.y << 7;
    const int ar = t >> 1, ac8 = (t & 1) << 3;
    const int bk = t >> 4;
    const int bn = (TN == 128) ? ((t & 15) << 3) : ((t & 15) << 2);
    const int tyo = (t >> 4) << 3, txo = (t & 15) * NW;
    if (GATHER) { if (t < 128) toks[t] = tok[m0 + t]; __syncthreads(); }
    const float* arow = GATHER ? (emb + (size_t)toks[ar] * K)
                               : (A   + (size_t)(m0 + ar) * K);
    const float* brow = Bm + (size_t)bk * N + n0 + bn;

    u64 acc[8][NP];
#pragma unroll
    for (int i = 0; i < 8; i++)
#pragma unroll
        for (int j = 0; j < NP; j++) acc[i][j] = 0ull;

    float4 av0 = *(const float4*)(arow + ac8);
    float4 av1 = *(const float4*)(arow + ac8 + 4);
    float4 bv0 = *(const float4*)(brow);
    float4 bv1;
    if (TN == 128) bv1 = *(const float4*)(brow + 4);

    int s = 0, k0 = 0;
    while (true) {
        AsT[s][ac8+0][ar]=av0.x; AsT[s][ac8+1][ar]=av0.y;
        AsT[s][ac8+2][ar]=av0.z; AsT[s][ac8+3][ar]=av0.w;
        AsT[s][ac8+4][ar]=av1.x; AsT[s][ac8+5][ar]=av1.y;
        AsT[s][ac8+6][ar]=av1.z; AsT[s][ac8+7][ar]=av1.w;
        *(float4*)(&Bs[s][bk][bn]) = bv0;
        if (TN == 128) *(float4*)(&Bs[s][bk][bn+4]) = bv1;
        __syncthreads();
        k0 += 16;
        const bool more = (k0 < K);
        if (more) {
            av0 = *(const float4*)(arow + k0 + ac8);
            av1 = *(const float4*)(arow + k0 + ac8 + 4);
            bv0 = *(const float4*)(brow + (size_t)k0 * N);
            if (TN == 128) bv1 = *(const float4*)(brow + (size_t)k0 * N + 4);
        }
#pragma unroll
        for (int kk = 0; kk < 16; kk++) {
            float4 af0 = *(const float4*)(&AsT[s][kk][tyo]);
            float4 af1 = *(const float4*)(&AsT[s][kk][tyo + 4]);
            u64 a2[8];
            a2[0]=pk2(af0.x); a2[1]=pk2(af0.y); a2[2]=pk2(af0.z); a2[3]=pk2(af0.w);
            a2[4]=pk2(af1.x); a2[5]=pk2(af1.y); a2[6]=pk2(af1.z); a2[7]=pk2(af1.w);
            u64 bp[NP];
            {
                ulonglong2 bb0 = *(const ulonglong2*)(&Bs[s][kk][txo]);
                bp[0] = bb0.x; bp[1] = bb0.y;
                if (TN == 128) {
                    ulonglong2 bb1 = *(const ulonglong2*)(&Bs[s][kk][txo + 4]);
                    bp[2] = bb1.x; bp[3] = bb1.y;
                }
            }
#pragma unroll
            for (int i = 0; i < 8; i++)
#pragma unroll
                for (int j = 0; j < NP; j++) f2(acc[i][j], a2[i], bp[j]);
        }
        if (!more) break;
        s ^= 1;
    }
    float bb[NW];
#pragma unroll
    for (int j = 0; j < NW; j++) bb[j] = bias[n0 + txo + j];
#pragma unroll
    for (int i = 0; i < 8; i++) {
        float ov[NW];
#pragma unroll
        for (int j = 0; j < NP; j++) {
            float lo, hi;
            upk2(acc[i][j], lo, hi);
            ov[2*j]   = lo + bb[2*j];
            ov[2*j+1] = hi + bb[2*j+1];
        }
        if (RELU) {
#pragma unroll
            for (int j = 0; j < NW; j++) ov[j] = fmaxf(ov[j], 0.f);
        }
        float* cp = C + (size_t)(m0 + tyo + i) * N + n0 + txo;
        *(float4*)cp = make_float4(ov[0], ov[1], ov[2], ov[3]);
        if (TN == 128) *(float4*)(cp + 4) = make_float4(ov[4], ov[5], ov[6], ov[7]);
    }
}

// ---------------------------------------------------------------------------
// QLSTM recurrence: cluster of 8, W in registers, st.async exchange with
// v4.b32 stores (256 tx/barrier instead of 1024 — tx-serialization fix).
// ---------------------------------------------------------------------------
#define LSTM_SMEM_FLOATS (8*132 + 2*8*132 + 256 + 256 + 8 + 8)
__global__ __cluster_dims__(8,1,1) __launch_bounds__(256)
void lstm_kernel(const float* __restrict__ W, float* __restrict__ hseq)
{
    extern __shared__ float sm[];
    float* red  = sm;                          // [8][132]
    float* allq = red + 8*132;                 // [2][8][132]
    float* hx   = allq + 2*8*132;              // [256]
    float* cx   = hx + 256;                    // [256]
    float* wtot = cx + 256;                    // [8]
    u64*   mbar = (u64*)(wtot + 8);            // [2]

    cg::cluster_group cluster = cg::this_cluster();
    const int rank = (int)cluster.block_rank();
    const int g    = rank >> 1, half = rank & 1;
    const int b    = blockIdx.x >> 3;
    const int t    = threadIdx.x;
    const int ks   = t >> 5, jc = t & 31;
    const int lane = t & 31, w = t >> 5;

    const uint32_t allq32 = smem_u32(allq);
    const uint32_t mbar32 = smem_u32(mbar);

    if (t == 0) {
        asm volatile("mbarrier.init.shared.b64 [%0], 1;" :: "r"(mbar32) : "memory");
        asm volatile("mbarrier.init.shared.b64 [%0], 1;" :: "r"(mbar32 + 8) : "memory");
    }

    const float* gW = W + g * 131072 + 65536 + half * 128;
    ulonglong2 wr[32];
#pragma unroll
    for (int kk = 0; kk < 32; kk++)
        wr[kk] = *(const ulonglong2*)(gW + (size_t)((kk << 3) + ks) * 256 + (jc << 2));

    hx[t] = 0.f; cx[t] = 0.f;

    float pediv = __expf((float)((t >> 1) << 1) * (-9.210340371976184f / 256.f));

    uint32_t paq[8], pmb[8];
#pragma unroll
    for (int r = 0; r < 8; r++) {
        asm("mapa.shared::cluster.u32 %0, %1, %2;" : "=r"(paq[r]) : "r"(allq32), "r"(r));
        asm("mapa.shared::cluster.u32 %0, %1, %2;" : "=r"(pmb[r]) : "r"(mbar32), "r"(r));
    }

    __syncthreads();
    cluster.sync();   // barriers visible before any push

    const float* zxp = g_zx + (size_t)b * 256 * 1024 + g * 256 + half * 128;
    float zcur = (t < 128) ? zxp[t] : 0.f;

    for (int step = 0; step < 256; ++step) {
        const int par = step & 1;
        // ---- dot: hx @ Wslice, all from registers ----
        u64 acc01 = 0ull, acc23 = 0ull;
#pragma unroll
        for (int kk = 0; kk < 32; ++kk) {
            u64 hv2 = pk2(hx[(kk << 3) + ks]);
            f2(acc01, hv2, wr[kk].x);
            f2(acc23, hv2, wr[kk].y);
        }
        float znext = 0.f;
        if (t < 128) {
            int sn = (step < 255) ? step + 1 : step;
            znext = zxp[(size_t)sn * 1024 + t];
        }
        {
            float a0, a1, a2, a3;
            upk2(acc01, a0, a1); upk2(acc23, a2, a3);
            *(float4*)&red[ks * 132 + (jc << 2)] = make_float4(a0, a1, a2, a3);
        }
        __syncthreads();
        // ---- z, cos, local cumprod over 128 cols ----
        float p = 0.f;
        if (t < 128) {
            float z = red[t] + red[132 + t] + red[264 + t] + red[396 + t]
                    + red[528 + t] + red[660 + t] + red[792 + t] + red[924 + t]
                    + zcur;
            p = __cosf(z);
#pragma unroll
            for (int off = 1; off < 32; off <<= 1) {
                float u = __shfl_up_sync(0xffffffffu, p, off);
                if (lane >= off) p *= u;
            }
            if (lane == 31) wtot[w] = p;
        }
        zcur = znext;
        __syncthreads();
        if (t == 0) {
            asm volatile("mbarrier.arrive.expect_tx.shared.b64 _, [%0], 4096;"
                         :: "r"(mbar32 + par * 8) : "memory");
        }
        if (t < 128) {
            float pre = 1.f;
            for (int ww = 0; ww < w; ++ww) pre *= wtot[ww];
            float sv = p * pre;
            // gather 4 consecutive scanned values into lanes 0..7 of each warp
            float v0 = __shfl_sync(0xffffffffu, sv, (lane & 7) * 4 + 0);
            float v1 = __shfl_sync(0xffffffffu, sv, (lane & 7) * 4 + 1);
            float v2 = __shfl_sync(0xffffffffu, sv, (lane & 7) * 4 + 2);
            float v3 = __shfl_sync(0xffffffffu, sv, (lane & 7) * 4 + 3);
            if (lane < 8) {
                const uint32_t off4 =
                    (uint32_t)(par * 1056 + rank * 132 + (w << 5) + (lane << 2)) * 4u;
                const uint32_t b0 = __float_as_uint(v0), b1 = __float_as_uint(v1);
                const uint32_t b2 = __float_as_uint(v2), b3 = __float_as_uint(v3);
#pragma unroll
                for (int r = 0; r < 8; r++) {
                    asm volatile(
                        "st.async.shared::cluster.mbarrier::complete_tx::bytes.v4.b32 "
                        "[%0], {%1, %2, %3, %4}, [%5];"
                        :: "r"(paq[r] + off4), "r"(b0), "r"(b1), "r"(b2), "r"(b3),
                           "r"(pmb[r] + par * 8) : "memory");
                }
            }
        }
        mbar_wait_cluster(mbar32 + par * 8, (uint32_t)((step >> 1) & 1));
        // ---- gates from LOCAL allq + state update (replicated) ----
        {
            const int sh = t >> 7, off = t & 127;
            const float* aq = allq + par * 1056;
            float qg4[4];
#pragma unroll
            for (int gg = 0; gg < 4; gg++) {
                float v = aq[(gg * 2 + sh) * 132 + off];
                if (sh) v *= aq[(gg * 2) * 132 + 127];
                qg4[gg] = v;
            }
            float f  = sigm_f(qg4[0]);
            float ii = sigm_f(qg4[1]);
            float gg = tanh_f(qg4[2]);
            float oo = sigm_f(qg4[3]);
            float cn = f * cx[t] + ii * gg;
            cx[t] = cn;
            float hn = oo * tanh_f(cn);
            hx[t] = hn;
            if (rank == 0) {
                float ang = (float)step * pediv;
                float pe  = (t & 1) ? __cosf(ang) : __sinf(ang);
                hseq[((size_t)b * 256 + step) * 256 + t] = hn + pe;
            }
        }
        __syncthreads();
    }
    cluster.sync();
}

// fused q/k/v qproj: one warp per row, reads h once, writes 3 outputs
__global__ void qproj3_kernel(const float* __restrict__ h, const float* __restrict__ th,
                              float* __restrict__ qo, float* __restrict__ ko,
                              float* __restrict__ vo) {
    const int w = threadIdx.x >> 5, lane = threadIdx.x & 31;
    const int row = blockIdx.x * 8 + w;
    const float* hr = h + (size_t)row * 256 + lane * 8;
    float4 h0 = *(const float4*)hr, h1 = *(const float4*)(hr + 4);
    float* outs[3] = {qo, ko, vo};
#pragma unroll
    for (int c = 0; c < 3; c++) {
        const float* tr = th + c * 256 + lane * 8;
        float4 t0 = *(const float4*)tr, t1 = *(const float4*)(tr + 4);
        float p[8], run;
        run  = __cosf(h0.x+t0.x); p[0]=run;  run *= __cosf(h0.y+t0.y); p[1]=run;
        run *= __cosf(h0.z+t0.z); p[2]=run;  run *= __cosf(h0.w+t0.w); p[3]=run;
        run *= __cosf(h1.x+t1.x); p[4]=run;  run *= __cosf(h1.y+t1.y); p[5]=run;
        run *= __cosf(h1.z+t1.z); p[6]=run;  run *= __cosf(h1.w+t1.w); p[7]=run;
        float incl = run;
#pragma unroll
        for (int off = 1; off < 32; off <<= 1) {
            float u = __shfl_up_sync(0xffffffffu, incl, off);
            if (lane >= off) incl *= u;
        }
        float ex = __shfl_up_sync(0xffffffffu, incl, 1);
        if (lane == 0) ex = 1.f;
        float* o = outs[c] + (size_t)row * 256 + lane * 8;
        *(float4*)o     = make_float4(ex*p[0], ex*p[1], ex*p[2], ex*p[3]);
        *(float4*)(o+4) = make_float4(ex*p[4], ex*p[5], ex*p[6], ex*p[7]);
    }
}

// fused attention, 2-row blocking per warp, FFMA2 inner products
#define ATTN_SMEM (36864 + 33280 + 16384 + 2048)
__global__ __launch_bounds__(256) void attn_kernel(const float* __restrict__ Q,
    const float* __restrict__ K, const float* __restrict__ V, float* __restrict__ O)
{
    extern __shared__ float sm[];
    float* kh = sm;               // [256][36]
    float* vt = sm + 256 * 36;    // [32][260]
    float* ps = vt + 32 * 260;    // [8][2][256]
    float* qs = ps + 8 * 512;     // [8][64]
    const int b = blockIdx.x >> 3, hh = blockIdx.x & 7;
    const int t = threadIdx.x, w = t >> 5, lane = t & 31;
    const size_t base = ((size_t)b * 256) * 256 + hh * 32;
    for (int idx = t; idx < 8192; idx += 256) {
        int kr = idx >> 5, d = idx & 31;
        size_t go = base + (size_t)kr * 256 + d;
        kh[kr * 36 + d]  = K[go];
        vt[d * 260 + kr] = V[go];
    }
    __syncthreads();
    float* qsw = qs + w * 64;
    float* ps0 = ps + w * 512;
    float* ps1 = ps0 + 256;
    for (int i = 0; i < 16; i++) {
        const int r0 = w + 8 * i, r1 = r0 + 128;
        qsw[lane]      = Q[base + (size_t)r0 * 256 + lane];
        qsw[32 + lane] = Q[base + (size_t)r1 * 256 + lane];
        __syncwarp();
        u64 qa[16], qb[16];
        {
            const ulonglong2* qp = (const ulonglong2*)qsw;
#pragma unroll
            for (int u = 0; u < 8; u++) {
                ulonglong2 v0 = qp[u];     qa[2*u] = v0.x; qa[2*u+1] = v0.y;
                ulonglong2 v1 = qp[u + 8]; qb[2*u] = v1.x; qb[2*u+1] = v1.y;
            }
        }
        float s0[8], s1[8];
#pragma unroll
        for (int c = 0; c < 8; c++) {
            const ulonglong2* kp = (const ulonglong2*)(kh + (c * 32 + lane) * 36);
            u64 a0 = 0ull, a1 = 0ull;
#pragma unroll
            for (int u = 0; u < 8; u++) {
                ulonglong2 kv = kp[u];
                f2(a0, qa[2*u], kv.x); f2(a0, qa[2*u+1], kv.y);
                f2(a1, qb[2*u], kv.x); f2(a1, qb[2*u+1], kv.y);
            }
            float lo, hi;
            upk2(a0, lo, hi); s0[c] = (lo + hi) * 0.17677669529663689f;
            upk2(a1, lo, hi); s1[c] = (lo + hi) * 0.17677669529663689f;
        }
        float m0 = s0[0], m1 = s1[0];
#pragma unroll
        for (int c = 1; c < 8; c++) { m0 = fmaxf(m0, s0[c]); m1 = fmaxf(m1, s1[c]); }
#pragma unroll
        for (int off = 16; off; off >>= 1) {
            m0 = fmaxf(m0, __shfl_xor_sync(0xffffffffu, m0, off));
            m1 = fmaxf(m1, __shfl_xor_sync(0xffffffffu, m1, off));
        }
        float sum0 = 0.f, sum1 = 0.f;
#pragma unroll
        for (int c = 0; c < 8; c++) {
            s0[c] = __expf(s0[c] - m0); sum0 += s0[c];
            s1[c] = __expf(s1[c] - m1); sum1 += s1[c];
        }
#pragma unroll
        for (int off = 16; off; off >>= 1) {
            sum0 += __shfl_xor_sync(0xffffffffu, sum0, off);
            sum1 += __shfl_xor_sync(0xffffffffu, sum1, off);
        }
#pragma unroll
        for (int c = 0; c < 8; c++) {
            ps0[c * 32 + lane] = s0[c];
            ps1[c * 32 + lane] = s1[c];
        }
        __syncwarp();
        u64 a0 = 0ull, a1 = 0ull;
        const ulonglong2* pp0 = (const ulonglong2*)ps0;
        const ulonglong2* pp1 = (const ulonglong2*)ps1;
        const ulonglong2* vp  = (const ulonglong2*)(vt + lane * 260);
#pragma unroll
        for (int k8 = 0; k8 < 64; k8++) {
            ulonglong2 vv = vp[k8];
            ulonglong2 p0 = pp0[k8];
            ulonglong2 p1 = pp1[k8];
            f2(a0, p0.x, vv.x); f2(a0, p0.y, vv.y);
            f2(a1, p1.x, vv.x); f2(a1, p1.y, vv.y);
        }
        float lo, hi;
        upk2(a0, lo, hi); O[base + (size_t)r0 * 256 + lane] = (lo + hi) / sum0;
        upk2(a1, lo, hi); O[base + (size_t)r1 * 256 + lane] = (lo + hi) / sum1;
        __syncwarp();
    }
}

// residual add + LayerNorm; optionally fused qproj of the LN output (NQ outputs)
template<int NQ>
__global__ void resid_ln_kernel(float* __restrict__ h, const float* __restrict__ d,
                                const float* __restrict__ gw, const float* __restrict__ bw,
                                const float* __restrict__ th,
                                float* __restrict__ q0, float* __restrict__ q1,
                                float* __restrict__ q2) {
    const int row = blockIdx.x, j = threadIdx.x, w = j >> 5, lane = j & 31;
    __shared__ float ssum[8], ssq[8], wt[3][8];
    size_t off = (size_t)row * 256 + j;
    float v = h[off] + d[off];
    float s = v, s2 = v * v;
#pragma unroll
    for (int o = 16; o; o >>= 1) {
        s  += __shfl_xor_sync(0xffffffffu, s, o);
        s2 += __shfl_xor_sync(0xffffffffu, s2, o);
    }
    if (lane == 0) { ssum[w] = s; ssq[w] = s2; }
    __syncthreads();
    if (j == 0) {
        float S = 0.f, S2 = 0.f;
        for (int i = 0; i < 8; i++) { S += ssum[i]; S2 += ssq[i]; }
        ssum[0] = S; ssq[0] = S2;
    }
    __syncthreads();
    float mean = ssum[0] * (1.f/256.f);
    float var  = ssq[0]  * (1.f/256.f) - mean * mean;
    float nv = (v - mean) * rsqrtf(var + 1e-5f) * gw[j] + bw[j];
    h[off] = nv;
    if (NQ > 0) {
        float* outs[3] = {q0, q1, q2};
#pragma unroll
        for (int c = 0; c < NQ; c++) {
            float p = __cosf(nv + th[c * 256 + j]);
#pragma unroll
            for (int o = 1; o < 32; o <<= 1) {
                float u = __shfl_up_sync(0xffffffffu, p, o);
                if (lane >= o) p *= u;
            }
            if (lane == 31) wt[c][w] = p;
            __syncthreads();
            float pre = 1.f;
            for (int ww = 0; ww < w; ++ww) pre *= wt[c][ww];
            outs[c][off] = p * pre;
        }
    }
}

__global__ void pool_cls_kernel(const float* __restrict__ h, const float* __restrict__ Wc,
                                const float* __restrict__ bc, float* __restrict__ out) {
    __shared__ float pooled[256];
    const int b = blockIdx.x, e = threadIdx.x;
    float s = 0.f;
    for (int tt = 0; tt < 256; ++tt) s += h[((size_t)b * 256 + tt) * 256 + e];
    pooled[e] = s * (1.f/256.f);
    __syncthreads();
    if (e < 4) {
        float a = bc[e];
        for (int i = 0; i < 256; i++) a = fmaf(pooled[i], Wc[i * 4 + e], a);
        out[b * 4 + e] = a;
    }
}

extern "C" void kernel_launch(void* const* d_in, const int* in_sizes, int n_in,
                              void* d_out, int out_size)
{
    const int*   x      = (const int*)  d_in[0];
    const float* tokemb = (const float*)d_in[1];
    const float* lstmW  = (const float*)d_in[2];
    const float* lstmB  = (const float*)d_in[3];
    const float* lstmTh = (const float*)d_in[4];
    const float* ln1g   = (const float*)d_in[5];
    const float* ln1b   = (const float*)d_in[6];
    const float* ln2g   = (const float*)d_in[7];
    const float* ln2b   = (const float*)d_in[8];
    const float* qkvTh  = (const float*)d_in[9];
    const float* combW  = (const float*)d_in[10];
    const float* combB  = (const float*)d_in[11];
    const float* ffnTh  = (const float*)d_in[12];
    const float* lin1W  = (const float*)d_in[13];
    const float* lin1B  = (const float*)d_in[14];
    const float* lin2W  = (const float*)d_in[15];
    const float* lin2B  = (const float*)d_in[16];
    const float* clsW   = (const float*)d_in[17];
    const float* clsB   = (const float*)d_in[18];
    float* out = (float*)d_out;

    float *p_zx,*p_wxp,*p_bth,*p_h,*p_q,*p_k,*p_v,*p_at,*p_ffq,*p_t1,*p_t2;
    cudaGetSymbolAddress((void**)&p_zx,  g_zx);
    cudaGetSymbolAddress((void**)&p_wxp, g_wxp);
    cudaGetSymbolAddress((void**)&p_bth, g_bth);
    cudaGetSymbolAddress((void**)&p_h,   g_h);
    cudaGetSymbolAddress((void**)&p_q,   g_q);
    cudaGetSymbolAddress((void**)&p_k,   g_k);
    cudaGetSymbolAddress((void**)&p_v,   g_v);
    cudaGetSymbolAddress((void**)&p_at,  g_at);
    cudaGetSymbolAddress((void**)&p_ffq, g_ffq);
    cudaGetSymbolAddress((void**)&p_t1,  g_t1);
    cudaGetSymbolAddress((void**)&p_t2,  g_t2);

    cudaFuncSetAttribute(attn_kernel, cudaFuncAttributeMaxDynamicSharedMemorySize, ATTN_SMEM);
    cudaFuncSetAttribute(lstm_kernel, cudaFuncAttributeMaxDynamicSharedMemorySize,
                         LSTM_SMEM_FLOATS * 4);

    pack_w_kernel<<<1024, 256>>>(lstmW);
    pack_b_kernel<<<4, 256>>>(lstmB, lstmTh);
    gemm_kernel<128, true, false><<<dim3(8, 32), 256>>>(
        nullptr, p_wxp, p_zx, ROWS, 1024, 256, p_bth, x, tokemb);
    lstm_kernel<<<128, 256, LSTM_SMEM_FLOATS * 4>>>(lstmW, p_h);

    // ---- layer 0 ----
    qproj3_kernel<<<ROWS/8, 256>>>(p_h, qkvTh, p_q, p_k, p_v);
    attn_kernel<<<Bb*8, 256, ATTN_SMEM>>>(p_q, p_k, p_v, p_at);
    gemm_kernel<64, false, false><<<dim3(4, 32), 256>>>(
        p_at, combW, p_t2, ROWS, 256, 256, combB, nullptr, nullptr);
    resid_ln_kernel<1><<<ROWS, 256>>>(p_h, p_t2, ln1g, ln1b, ffnTh,
                                      p_ffq, nullptr, nullptr);
    gemm_kernel<128, false, true><<<dim3(8, 32), 256>>>(
        p_ffq, lin1W, p_t1, ROWS, 1024, 256, lin1B, nullptr, nullptr);
    gemm_kernel<64, false, false><<<dim3(4, 32), 256>>>(
        p_t1, lin2W, p_t2, ROWS, 256, 1024, lin2B, nullptr, nullptr);
    resid_ln_kernel<3><<<ROWS, 256>>>(p_h, p_t2, ln2g, ln2b, qkvTh + 3*256,
                                      p_q, p_k, p_v);

    // ---- layer 1 ----
    attn_kernel<<<Bb*8, 256, ATTN_SMEM>>>(p_q, p_k, p_v, p_at);
    gemm_kernel<64, false, false><<<dim3(4, 32), 256>>>(
        p_at, combW + 256*256, p_t2, ROWS, 256, 256, combB + 256, nullptr, nullptr);
    resid_ln_kernel<1><<<ROWS, 256>>>(p_h, p_t2, ln1g + 256, ln1b + 256,
                                      ffnTh + 256, p_ffq, nullptr, nullptr);
    gemm_kernel<128, false, true><<<dim3(8, 32), 256>>>(
        p_ffq, lin1W + 256*1024, p_t1, ROWS, 1024, 256, lin1B + 1024,
        nullptr, nullptr);
    gemm_kernel<64, false, false><<<dim3(4, 32), 256>>>(
        p_t1, lin2W + 1024*256, p_t2, ROWS, 256, 1024, lin2B + 256,
        nullptr, nullptr);
    resid_ln_kernel<0><<<ROWS, 256>>>(p_h, p_t2, ln2g + 256, ln2b + 256,
                                      nullptr, nullptr, nullptr, nullptr);

    pool_cls_kernel<<<Bb, 256>>>(p_h, clsW, clsB, out);
}

// round 13
// speedup vs baseline: 2.1007x; 1.1431x over previous
#include <cuda_runtime.h>
#include <math.h>
#include <cooperative_groups.h>
namespace cg = cooperative_groups;

#define Bb 16
#define Ss 256
#define Ee 256
#define ROWS (Bb*Ss)
#define FFNf 1024

typedef unsigned long long u64;

__device__ float g_zx [ROWS*1024];
__device__ float g_wxp[256*1024];
__device__ float g_bth[1024];
__device__ float g_h  [ROWS*Ee];
__device__ float g_q  [ROWS*Ee];
__device__ float g_k  [ROWS*Ee];
__device__ float g_v  [ROWS*Ee];
__device__ float g_at [ROWS*Ee];
__device__ float g_ffq[ROWS*Ee];
__device__ float g_t1 [ROWS*FFNf];
__device__ float g_t2 [ROWS*Ee];

__device__ __forceinline__ float sigm_f(float x) { return 1.f / (1.f + __expf(-x)); }
__device__ __forceinline__ float tanh_f(float x) {
    float t = __expf(-2.f * x);
    return (1.f - t) / (1.f + t);
}
// sigmoid on [-1,1]: odd Taylor about 0, |err| < 2.2e-6. Pure FMA (0 MUFU).
__device__ __forceinline__ float sigm_poly(float x) {
    float x2 = x * x;
    float p = fmaf(x2, 2.13569388e-5f, -2.10813492e-4f);
    p = fmaf(x2, p, 2.08333333e-3f);
    p = fmaf(x2, p, -2.08333333e-2f);
    p = fmaf(x2, p, 0.25f);
    return fmaf(x, p, 0.5f);
}
// tanh on [-1,1]: Pade [5/4], |err| ~ 1e-7. 1 MUFU (fast division).
__device__ __forceinline__ float tanh_poly(float x) {
    float x2 = x * x;
    float num = x * fmaf(x2, fmaf(x2, 1.f, 105.f), 945.f);
    float den = fmaf(x2, fmaf(x2, 15.f, 420.f), 945.f);
    return __fdividef(num, den);
}
// tanh for |x| <= ~2.5 (cell state): exp-based, fast division. 2 MUFU.
__device__ __forceinline__ float tanh_fast(float x) {
    float t = __expf(-2.f * x);
    return __fdividef(1.f - t, 1.f + t);
}

// ---- packed fp32x2 helpers (sm_103a FFMA2) ----
__device__ __forceinline__ u64 pk2(float x) {
    u64 r; asm("mov.b64 %0, {%1, %1};" : "=l"(r) : "f"(x)); return r;
}
__device__ __forceinline__ void f2(u64& a, u64 x, u64 y) {
    asm("fma.rn.f32x2 %0, %1, %2, %0;" : "+l"(a) : "l"(x), "l"(y));
}
__device__ __forceinline__ void upk2(u64 v, float& lo, float& hi) {
    asm("mov.b64 {%0, %1}, %2;" : "=f"(lo), "=f"(hi) : "l"(v));
}
__device__ __forceinline__ uint32_t smem_u32(const void* p) {
    uint32_t a;
    asm("{ .reg .u64 t; cvta.to.shared.u64 t, %1; cvt.u32.u64 %0, t; }"
        : "=r"(a) : "l"(p));
    return a;
}
__device__ __forceinline__ void mbar_wait_cluster(uint32_t mbar, uint32_t ph) {
    asm volatile(
        "{\n\t.reg .pred P;\n"
        "LW_%=:\n\t"
        "mbarrier.try_wait.parity.acquire.cluster.shared::cta.b64 P, [%0], %1, 0x989680;\n\t"
        "@P bra.uni LD_%=;\n\t"
        "bra.uni LW_%=;\n"
        "LD_%=:\n\t}"
        :: "r"(mbar), "r"(ph) : "memory");
}

// pack Wx -> [k][g*256+j]
__global__ void pack_w_kernel(const float* __restrict__ W) {
    int idx = blockIdx.x * 256 + threadIdx.x;
    int k = idx >> 10, n = idx & 1023, g = n >> 8, j = n & 255;
    g_wxp[idx] = W[g * 131072 + k * 256 + j];
}
// fold b+theta
__global__ void pack_b_kernel(const float* __restrict__ B, const float* __restrict__ Th) {
    int idx = blockIdx.x * 256 + threadIdx.x;
    g_bth[idx] = B[idx] + Th[idx];
}

// ---- fp32 GEMM (round-8 proven config): 128xTN tile, 256 thr, 8x(TN/16) micro ----
template<int TN, bool GATHER, bool RELU>
__global__ __launch_bounds__(256) void gemm_kernel(
    const float* __restrict__ A, const float* __restrict__ Bm, float* __restrict__ C,
    int M, int N, int K, const float* __restrict__ bias,
    const int* __restrict__ tok, const float* __restrict__ emb)
{
    constexpr int NW = TN / 16;   // 8 or 4
    constexpr int NP = NW / 2;
    __shared__ float AsT[2][16][136];
    __shared__ float Bs [2][16][136];
    __shared__ int   toks[128];
    const int t = threadIdx.x;
    const int n0 = blockIdx.x * TN, m0 = blockIdx.y << 7;
    const int ar = t >> 1, ac8 = (t & 1) << 3;
    const int bk = t >> 4;
    const int bn = (TN == 128) ? ((t & 15) << 3) : ((t & 15) << 2);
    const int tyo = (t >> 4) << 3, txo = (t & 15) * NW;
    if (GATHER) { if (t < 128) toks[t] = tok[m0 + t]; __syncthreads(); }
    const float* arow = GATHER ? (emb + (size_t)toks[ar] * K)
                               : (A   + (size_t)(m0 + ar) * K);
    const float* brow = Bm + (size_t)bk * N + n0 + bn;

    u64 acc[8][NP];
#pragma unroll
    for (int i = 0; i < 8; i++)
#pragma unroll
        for (int j = 0; j < NP; j++) acc[i][j] = 0ull;

    float4 av0 = *(const float4*)(arow + ac8);
    float4 av1 = *(const float4*)(arow + ac8 + 4);
    float4 bv0 = *(const float4*)(brow);
    float4 bv1;
    if (TN == 128) bv1 = *(const float4*)(brow + 4);

    int s = 0, k0 = 0;
    while (true) {
        AsT[s][ac8+0][ar]=av0.x; AsT[s][ac8+1][ar]=av0.y;
        AsT[s][ac8+2][ar]=av0.z; AsT[s][ac8+3][ar]=av0.w;
        AsT[s][ac8+4][ar]=av1.x; AsT[s][ac8+5][ar]=av1.y;
        AsT[s][ac8+6][ar]=av1.z; AsT[s][ac8+7][ar]=av1.w;
        *(float4*)(&Bs[s][bk][bn]) = bv0;
        if (TN == 128) *(float4*)(&Bs[s][bk][bn+4]) = bv1;
        __syncthreads();
        k0 += 16;
        const bool more = (k0 < K);
        if (more) {
            av0 = *(const float4*)(arow + k0 + ac8);
            av1 = *(const float4*)(arow + k0 + ac8 + 4);
            bv0 = *(const float4*)(brow + (size_t)k0 * N);
            if (TN == 128) bv1 = *(const float4*)(brow + (size_t)k0 * N + 4);
        }
#pragma unroll
        for (int kk = 0; kk < 16; kk++) {
            float4 af0 = *(const float4*)(&AsT[s][kk][tyo]);
            float4 af1 = *(const float4*)(&AsT[s][kk][tyo + 4]);
            u64 a2[8];
            a2[0]=pk2(af0.x); a2[1]=pk2(af0.y); a2[2]=pk2(af0.z); a2[3]=pk2(af0.w);
            a2[4]=pk2(af1.x); a2[5]=pk2(af1.y); a2[6]=pk2(af1.z); a2[7]=pk2(af1.w);
            u64 bp[NP];
            {
                ulonglong2 bb0 = *(const ulonglong2*)(&Bs[s][kk][txo]);
                bp[0] = bb0.x; bp[1] = bb0.y;
                if (TN == 128) {
                    ulonglong2 bb1 = *(const ulonglong2*)(&Bs[s][kk][txo + 4]);
                    bp[2] = bb1.x; bp[3] = bb1.y;
                }
            }
#pragma unroll
            for (int i = 0; i < 8; i++)
#pragma unroll
                for (int j = 0; j < NP; j++) f2(acc[i][j], a2[i], bp[j]);
        }
        if (!more) break;
        s ^= 1;
    }
    float bb[NW];
#pragma unroll
    for (int j = 0; j < NW; j++) bb[j] = bias[n0 + txo + j];
#pragma unroll
    for (int i = 0; i < 8; i++) {
        float ov[NW];
#pragma unroll
        for (int j = 0; j < NP; j++) {
            float lo, hi;
            upk2(acc[i][j], lo, hi);
            ov[2*j]   = lo + bb[2*j];
            ov[2*j+1] = hi + bb[2*j+1];
        }
        if (RELU) {
#pragma unroll
            for (int j = 0; j < NW; j++) ov[j] = fmaxf(ov[j], 0.f);
        }
        float* cp = C + (size_t)(m0 + tyo + i) * N + n0 + txo;
        *(float4*)cp = make_float4(ov[0], ov[1], ov[2], ov[3]);
        if (TN == 128) *(float4*)(cp + 4) = make_float4(ov[4], ov[5], ov[6], ov[7]);
    }
}

// ---------------------------------------------------------------------------
// QLSTM recurrence: cluster of 8, W in registers, scalar st.async exchange
// (r8-measured). Gate nonlinearities via polynomials (|q|<=1): MUFU per
// thread drops 10 -> 3 — the profiled bottleneck.
// ---------------------------------------------------------------------------
#define LSTM_SMEM_FLOATS (8*132 + 2*8*132 + 256 + 256 + 8 + 8)
__global__ __cluster_dims__(8,1,1) __launch_bounds__(256)
void lstm_kernel(const float* __restrict__ W, float* __restrict__ hseq)
{
    extern __shared__ float sm[];
    float* red  = sm;                          // [8][132]
    float* allq = red + 8*132;                 // [2][8][132]
    float* hx   = allq + 2*8*132;              // [256]
    float* cx   = hx + 256;                    // [256]
    float* wtot = cx + 256;                    // [8]
    u64*   mbar = (u64*)(wtot + 8);            // [2]

    cg::cluster_group cluster = cg::this_cluster();
    const int rank = (int)cluster.block_rank();
    const int g    = rank >> 1, half = rank & 1;
    const int b    = blockIdx.x >> 3;
    const int t    = threadIdx.x;
    const int ks   = t >> 5, jc = t & 31;
    const int lane = t & 31, w = t >> 5;

    const uint32_t allq32 = smem_u32(allq);
    const uint32_t mbar32 = smem_u32(mbar);

    if (t == 0) {
        asm volatile("mbarrier.init.shared.b64 [%0], 1;" :: "r"(mbar32) : "memory");
        asm volatile("mbarrier.init.shared.b64 [%0], 1;" :: "r"(mbar32 + 8) : "memory");
    }

    const float* gW = W + g * 131072 + 65536 + half * 128;
    ulonglong2 wr[32];
#pragma unroll
    for (int kk = 0; kk < 32; kk++)
        wr[kk] = *(const ulonglong2*)(gW + (size_t)((kk << 3) + ks) * 256 + (jc << 2));

    hx[t] = 0.f; cx[t] = 0.f;

    float pediv = __expf((float)((t >> 1) << 1) * (-9.210340371976184f / 256.f));

    uint32_t paq[8], pmb[8];
#pragma unroll
    for (int r = 0; r < 8; r++) {
        asm("mapa.shared::cluster.u32 %0, %1, %2;" : "=r"(paq[r]) : "r"(allq32), "r"(r));
        asm("mapa.shared::cluster.u32 %0, %1, %2;" : "=r"(pmb[r]) : "r"(mbar32), "r"(r));
    }

    __syncthreads();
    cluster.sync();   // barriers visible before any push

    const float* zxp = g_zx + (size_t)b * 256 * 1024 + g * 256 + half * 128;
    float zcur = (t < 128) ? zxp[t] : 0.f;

    for (int step = 0; step < 256; ++step) {
        const int par = step & 1;
        // ---- dot: hx @ Wslice, all from registers ----
        u64 acc01 = 0ull, acc23 = 0ull;
#pragma unroll
        for (int kk = 0; kk < 32; ++kk) {
            u64 hv2 = pk2(hx[(kk << 3) + ks]);
            f2(acc01, hv2, wr[kk].x);
            f2(acc23, hv2, wr[kk].y);
        }
        float znext = 0.f;
        if (t < 128) {
            int sn = (step < 255) ? step + 1 : step;
            znext = zxp[(size_t)sn * 1024 + t];
        }
        {
            float a0, a1, a2, a3;
            upk2(acc01, a0, a1); upk2(acc23, a2, a3);
            *(float4*)&red[ks * 132 + (jc << 2)] = make_float4(a0, a1, a2, a3);
        }
        __syncthreads();
        // ---- z, cos, local cumprod over 128 cols ----
        float p = 0.f;
        if (t < 128) {
            float z = red[t] + red[132 + t] + red[264 + t] + red[396 + t]
                    + red[528 + t] + red[660 + t] + red[792 + t] + red[924 + t]
                    + zcur;
            p = __cosf(z);
#pragma unroll
            for (int off = 1; off < 32; off <<= 1) {
                float u = __shfl_up_sync(0xffffffffu, p, off);
                if (lane >= off) p *= u;
            }
            if (lane == 31) wtot[w] = p;
        }
        zcur = znext;
        __syncthreads();
        if (t == 0) {
            asm volatile("mbarrier.arrive.expect_tx.shared.b64 _, [%0], 4096;"
                         :: "r"(mbar32 + par * 8) : "memory");
        }
        if (t < 128) {
            float pre = 1.f;
            for (int ww = 0; ww < w; ++ww) pre *= wtot[ww];
            float sv = p * pre;
            const uint32_t off4 = (uint32_t)(par * 1056 + rank * 132 + t) * 4u;
            const uint32_t svb = __float_as_uint(sv);
#pragma unroll
            for (int r = 0; r < 8; r++) {
                asm volatile(
                    "st.async.shared::cluster.mbarrier::complete_tx::bytes.b32 [%0], %1, [%2];"
                    :: "r"(paq[r] + off4), "r"(svb), "r"(pmb[r] + par * 8) : "memory");
            }
        }
        mbar_wait_cluster(mbar32 + par * 8, (uint32_t)((step >> 1) & 1));
        // ---- gates from LOCAL allq + state update (poly nonlinearities) ----
        {
            const int sh = t >> 7, off = t & 127;
            const float* aq = allq + par * 1056;
            float qg4[4];
#pragma unroll
            for (int gg = 0; gg < 4; gg++) {
                float v = aq[(gg * 2 + sh) * 132 + off];
                if (sh) v *= aq[(gg * 2) * 132 + 127];
                qg4[gg] = v;
            }
            float f  = sigm_poly(qg4[0]);
            float ii = sigm_poly(qg4[1]);
            float gg = tanh_poly(qg4[2]);
            float oo = sigm_poly(qg4[3]);
            float cn = f * cx[t] + ii * gg;
            cx[t] = cn;
            float hn = oo * tanh_fast(cn);
            hx[t] = hn;
            if (rank == 0) {
                float ang = (float)step * pediv;
                float pe  = (t & 1) ? __cosf(ang) : __sinf(ang);
                hseq[((size_t)b * 256 + step) * 256 + t] = hn + pe;
            }
        }
        __syncthreads();
    }
    cluster.sync();
}

// fused q/k/v qproj: one warp per row, reads h once, writes 3 outputs
__global__ void qproj3_kernel(const float* __restrict__ h, const float* __restrict__ th,
                              float* __restrict__ qo, float* __restrict__ ko,
                              float* __restrict__ vo) {
    const int w = threadIdx.x >> 5, lane = threadIdx.x & 31;
    const int row = blockIdx.x * 8 + w;
    const float* hr = h + (size_t)row * 256 + lane * 8;
    float4 h0 = *(const float4*)hr, h1 = *(const float4*)(hr + 4);
    float* outs[3] = {qo, ko, vo};
#pragma unroll
    for (int c = 0; c < 3; c++) {
        const float* tr = th + c * 256 + lane * 8;
        float4 t0 = *(const float4*)tr, t1 = *(const float4*)(tr + 4);
        float p[8], run;
        run  = __cosf(h0.x+t0.x); p[0]=run;  run *= __cosf(h0.y+t0.y); p[1]=run;
        run *= __cosf(h0.z+t0.z); p[2]=run;  run *= __cosf(h0.w+t0.w); p[3]=run;
        run *= __cosf(h1.x+t1.x); p[4]=run;  run *= __cosf(h1.y+t1.y); p[5]=run;
        run *= __cosf(h1.z+t1.z); p[6]=run;  run *= __cosf(h1.w+t1.w); p[7]=run;
        float incl = run;
#pragma unroll
        for (int off = 1; off < 32; off <<= 1) {
            float u = __shfl_up_sync(0xffffffffu, incl, off);
            if (lane >= off) incl *= u;
        }
        float ex = __shfl_up_sync(0xffffffffu, incl, 1);
        if (lane == 0) ex = 1.f;
        float* o = outs[c] + (size_t)row * 256 + lane * 8;
        *(float4*)o     = make_float4(ex*p[0], ex*p[1], ex*p[2], ex*p[3]);
        *(float4*)(o+4) = make_float4(ex*p[4], ex*p[5], ex*p[6], ex*p[7]);
    }
}

// fused attention, 2-row blocking per warp, FFMA2 inner products
#define ATTN_SMEM (36864 + 33280 + 16384 + 2048)
__global__ __launch_bounds__(256) void attn_kernel(const float* __restrict__ Q,
    const float* __restrict__ K, const float* __restrict__ V, float* __restrict__ O)
{
    extern __shared__ float sm[];
    float* kh = sm;               // [256][36]
    float* vt = sm + 256 * 36;    // [32][260]
    float* ps = vt + 32 * 260;    // [8][2][256]
    float* qs = ps + 8 * 512;     // [8][64]
    const int b = blockIdx.x >> 3, hh = blockIdx.x & 7;
    const int t = threadIdx.x, w = t >> 5, lane = t & 31;
    const size_t base = ((size_t)b * 256) * 256 + hh * 32;
    for (int idx = t; idx < 8192; idx += 256) {
        int kr = idx >> 5, d = idx & 31;
        size_t go = base + (size_t)kr * 256 + d;
        kh[kr * 36 + d]  = K[go];
        vt[d * 260 + kr] = V[go];
    }
    __syncthreads();
    float* qsw = qs + w * 64;
    float* ps0 = ps + w * 512;
    float* ps1 = ps0 + 256;
    for (int i = 0; i < 16; i++) {
        const int r0 = w + 8 * i, r1 = r0 + 128;
        qsw[lane]      = Q[base + (size_t)r0 * 256 + lane];
        qsw[32 + lane] = Q[base + (size_t)r1 * 256 + lane];
        __syncwarp();
        u64 qa[16], qb[16];
        {
            const ulonglong2* qp = (const ulonglong2*)qsw;
#pragma unroll
            for (int u = 0; u < 8; u++) {
                ulonglong2 v0 = qp[u];     qa[2*u] = v0.x; qa[2*u+1] = v0.y;
                ulonglong2 v1 = qp[u + 8]; qb[2*u] = v1.x; qb[2*u+1] = v1.y;
            }
        }
        float s0[8], s1[8];
#pragma unroll
        for (int c = 0; c < 8; c++) {
            const ulonglong2* kp = (const ulonglong2*)(kh + (c * 32 + lane) * 36);
            u64 a0 = 0ull, a1 = 0ull;
#pragma unroll
            for (int u = 0; u < 8; u++) {
                ulonglong2 kv = kp[u];
                f2(a0, qa[2*u], kv.x); f2(a0, qa[2*u+1], kv.y);
                f2(a1, qb[2*u], kv.x); f2(a1, qb[2*u+1], kv.y);
            }
            float lo, hi;
            upk2(a0, lo, hi); s0[c] = (lo + hi) * 0.17677669529663689f;
            upk2(a1, lo, hi); s1[c] = (lo + hi) * 0.17677669529663689f;
        }
        float m0 = s0[0], m1 = s1[0];
#pragma unroll
        for (int c = 1; c < 8; c++) { m0 = fmaxf(m0, s0[c]); m1 = fmaxf(m1, s1[c]); }
#pragma unroll
        for (int off = 16; off; off >>= 1) {
            m0 = fmaxf(m0, __shfl_xor_sync(0xffffffffu, m0, off));
            m1 = fmaxf(m1, __shfl_xor_sync(0xffffffffu, m1, off));
        }
        float sum0 = 0.f, sum1 = 0.f;
#pragma unroll
        for (int c = 0; c < 8; c++) {
            s0[c] = __expf(s0[c] - m0); sum0 += s0[c];
            s1[c] = __expf(s1[c] - m1); sum1 += s1[c];
        }
#pragma unroll
        for (int off = 16; off; off >>= 1) {
            sum0 += __shfl_xor_sync(0xffffffffu, sum0, off);
            sum1 += __shfl_xor_sync(0xffffffffu, sum1, off);
        }
#pragma unroll
        for (int c = 0; c < 8; c++) {
            ps0[c * 32 + lane] = s0[c];
            ps1[c * 32 + lane] = s1[c];
        }
        __syncwarp();
        u64 a0 = 0ull, a1 = 0ull;
        const ulonglong2* pp0 = (const ulonglong2*)ps0;
        const ulonglong2* pp1 = (const ulonglong2*)ps1;
        const ulonglong2* vp  = (const ulonglong2*)(vt + lane * 260);
#pragma unroll
        for (int k8 = 0; k8 < 64; k8++) {
            ulonglong2 vv = vp[k8];
            ulonglong2 p0 = pp0[k8];
            ulonglong2 p1 = pp1[k8];
            f2(a0, p0.x, vv.x); f2(a0, p0.y, vv.y);
            f2(a1, p1.x, vv.x); f2(a1, p1.y, vv.y);
        }
        float lo, hi;
        upk2(a0, lo, hi); O[base + (size_t)r0 * 256 + lane] = (lo + hi) / sum0;
        upk2(a1, lo, hi); O[base + (size_t)r1 * 256 + lane] = (lo + hi) / sum1;
        __syncwarp();
    }
}

// residual add + LayerNorm; optionally fused qproj of the LN output (NQ outputs)
template<int NQ>
__global__ void resid_ln_kernel(float* __restrict__ h, const float* __restrict__ d,
                                const float* __restrict__ gw, const float* __restrict__ bw,
                                const float* __restrict__ th,
                                float* __restrict__ q0, float* __restrict__ q1,
                                float* __restrict__ q2) {
    const int row = blockIdx.x, j = threadIdx.x, w = j >> 5, lane = j & 31;
    __shared__ float ssum[8], ssq[8], wt[3][8];
    size_t off = (size_t)row * 256 + j;
    float v = h[off] + d[off];
    float s = v, s2 = v * v;
#pragma unroll
    for (int o = 16; o; o >>= 1) {
        s  += __shfl_xor_sync(0xffffffffu, s, o);
        s2 += __shfl_xor_sync(0xffffffffu, s2, o);
    }
    if (lane == 0) { ssum[w] = s; ssq[w] = s2; }
    __syncthreads();
    if (j == 0) {
        float S = 0.f, S2 = 0.f;
        for (int i = 0; i < 8; i++) { S += ssum[i]; S2 += ssq[i]; }
        ssum[0] = S; ssq[0] = S2;
    }
    __syncthreads();
    float mean = ssum[0] * (1.f/256.f);
    float var  = ssq[0]  * (1.f/256.f) - mean * mean;
    float nv = (v - mean) * rsqrtf(var + 1e-5f) * gw[j] + bw[j];
    h[off] = nv;
    if (NQ > 0) {
        float* outs[3] = {q0, q1, q2};
#pragma unroll
        for (int c = 0; c < NQ; c++) {
            float p = __cosf(nv + th[c * 256 + j]);
#pragma unroll
            for (int o = 1; o < 32; o <<= 1) {
                float u = __shfl_up_sync(0xffffffffu, p, o);
                if (lane >= o) p *= u;
            }
            if (lane == 31) wt[c][w] = p;
            __syncthreads();
            float pre = 1.f;
            for (int ww = 0; ww < w; ++ww) pre *= wt[c][ww];
            outs[c][off] = p * pre;
        }
    }
}

__global__ void pool_cls_kernel(const float* __restrict__ h, const float* __restrict__ Wc,
                                const float* __restrict__ bc, float* __restrict__ out) {
    __shared__ float pooled[256];
    const int b = blockIdx.x, e = threadIdx.x;
    float s = 0.f;
    for (int tt = 0; tt < 256; ++tt) s += h[((size_t)b * 256 + tt) * 256 + e];
    pooled[e] = s * (1.f/256.f);
    __syncthreads();
    if (e < 4) {
        float a = bc[e];
        for (int i = 0; i < 256; i++) a = fmaf(pooled[i], Wc[i * 4 + e], a);
        out[b * 4 + e] = a;
    }
}

extern "C" void kernel_launch(void* const* d_in, const int* in_sizes, int n_in,
                              void* d_out, int out_size)
{
    const int*   x      = (const int*)  d_in[0];
    const float* tokemb = (const float*)d_in[1];
    const float* lstmW  = (const float*)d_in[2];
    const float* lstmB  = (const float*)d_in[3];
    const float* lstmTh = (const float*)d_in[4];
    const float* ln1g   = (const float*)d_in[5];
    const float* ln1b   = (const float*)d_in[6];
    const float* ln2g   = (const float*)d_in[7];
    const float* ln2b   = (const float*)d_in[8];
    const float* qkvTh  = (const float*)d_in[9];
    const float* combW  = (const float*)d_in[10];
    const float* combB  = (const float*)d_in[11];
    const float* ffnTh  = (const float*)d_in[12];
    const float* lin1W  = (const float*)d_in[13];
    const float* lin1B  = (const float*)d_in[14];
    const float* lin2W  = (const float*)d_in[15];
    const float* lin2B  = (const float*)d_in[16];
    const float* clsW   = (const float*)d_in[17];
    const float* clsB   = (const float*)d_in[18];
    float* out = (float*)d_out;

    float *p_zx,*p_wxp,*p_bth,*p_h,*p_q,*p_k,*p_v,*p_at,*p_ffq,*p_t1,*p_t2;
    cudaGetSymbolAddress((void**)&p_zx,  g_zx);
    cudaGetSymbolAddress((void**)&p_wxp, g_wxp);
    cudaGetSymbolAddress((void**)&p_bth, g_bth);
    cudaGetSymbolAddress((void**)&p_h,   g_h);
    cudaGetSymbolAddress((void**)&p_q,   g_q);
    cudaGetSymbolAddress((void**)&p_k,   g_k);
    cudaGetSymbolAddress((void**)&p_v,   g_v);
    cudaGetSymbolAddress((void**)&p_at,  g_at);
    cudaGetSymbolAddress((void**)&p_ffq, g_ffq);
    cudaGetSymbolAddress((void**)&p_t1,  g_t1);
    cudaGetSymbolAddress((void**)&p_t2,  g_t2);

    cudaFuncSetAttribute(attn_kernel, cudaFuncAttributeMaxDynamicSharedMemorySize, ATTN_SMEM);
    cudaFuncSetAttribute(lstm_kernel, cudaFuncAttributeMaxDynamicSharedMemorySize,
                         LSTM_SMEM_FLOATS * 4);

    pack_w_kernel<<<1024, 256>>>(lstmW);
    pack_b_kernel<<<4, 256>>>(lstmB, lstmTh);
    gemm_kernel<128, true, false><<<dim3(8, 32), 256>>>(
        nullptr, p_wxp, p_zx, ROWS, 1024, 256, p_bth, x, tokemb);
    lstm_kernel<<<128, 256, LSTM_SMEM_FLOATS * 4>>>(lstmW, p_h);

    // ---- layer 0 ----
    qproj3_kernel<<<ROWS/8, 256>>>(p_h, qkvTh, p_q, p_k, p_v);
    attn_kernel<<<Bb*8, 256, ATTN_SMEM>>>(p_q, p_k, p_v, p_at);
    gemm_kernel<64, false, false><<<dim3(4, 32), 256>>>(
        p_at, combW, p_t2, ROWS, 256, 256, combB, nullptr, nullptr);
    resid_ln_kernel<1><<<ROWS, 256>>>(p_h, p_t2, ln1g, ln1b, ffnTh,
                                      p_ffq, nullptr, nullptr);
    gemm_kernel<128, false, true><<<dim3(8, 32), 256>>>(
        p_ffq, lin1W, p_t1, ROWS, 1024, 256, lin1B, nullptr, nullptr);
    gemm_kernel<64, false, false><<<dim3(4, 32), 256>>>(
        p_t1, lin2W, p_t2, ROWS, 256, 1024, lin2B, nullptr, nullptr);
    resid_ln_kernel<3><<<ROWS, 256>>>(p_h, p_t2, ln2g, ln2b, qkvTh + 3*256,
                                      p_q, p_k, p_v);

    // ---- layer 1 ----
    attn_kernel<<<Bb*8, 256, ATTN_SMEM>>>(p_q, p_k, p_v, p_at);
    gemm_kernel<64, false, false><<<dim3(4, 32), 256>>>(
        p_at, combW + 256*256, p_t2, ROWS, 256, 256, combB + 256, nullptr, nullptr);
    resid_ln_kernel<1><<<ROWS, 256>>>(p_h, p_t2, ln1g + 256, ln1b + 256,
                                      ffnTh + 256, p_ffq, nullptr, nullptr);
    gemm_kernel<128, false, true><<<dim3(8, 32), 256>>>(
        p_ffq, lin1W + 256*1024, p_t1, ROWS, 1024, 256, lin1B + 1024,
        nullptr, nullptr);
    gemm_kernel<64, false, false><<<dim3(4, 32), 256>>>(
        p_t1, lin2W + 1024*256, p_t2, ROWS, 256, 1024, lin2B + 256,
        nullptr, nullptr);
    resid_ln_kernel<0><<<ROWS, 256>>>(p_h, p_t2, ln2g + 256, ln2b + 256,
                                      nullptr, nullptr, nullptr, nullptr);

    pool_cls_kernel<<<Bb, 256>>>(p_h, clsW, clsB, out);
}

// round 14
// speedup vs baseline: 2.1940x; 1.0444x over previous
#include <cuda_runtime.h>
#include <math.h>
#include <cooperative_groups.h>
namespace cg = cooperative_groups;

#define Bb 16
#define Ss 256
#define Ee 256
#define ROWS (Bb*Ss)
#define FFNf 1024

typedef unsigned long long u64;

__device__ float g_zx [ROWS*1024];
__device__ float g_wxp[256*1024];
__device__ float g_bth[1024];
__device__ float g_h  [ROWS*Ee];
__device__ float g_q  [ROWS*Ee];
__device__ float g_k  [ROWS*Ee];
__device__ float g_v  [ROWS*Ee];
__device__ float g_at [ROWS*Ee];
__device__ float g_ffq[ROWS*Ee];
__device__ float g_t1 [ROWS*FFNf];
__device__ float g_t2 [ROWS*Ee];

__device__ __forceinline__ float sigm_poly(float x) {
    float x2 = x * x;
    float p = fmaf(x2, 2.13569388e-5f, -2.10813492e-4f);
    p = fmaf(x2, p, 2.08333333e-3f);
    p = fmaf(x2, p, -2.08333333e-2f);
    p = fmaf(x2, p, 0.25f);
    return fmaf(x, p, 0.5f);
}
__device__ __forceinline__ float tanh_poly(float x) {
    float x2 = x * x;
    float num = x * fmaf(x2, fmaf(x2, 1.f, 105.f), 945.f);
    float den = fmaf(x2, fmaf(x2, 15.f, 420.f), 945.f);
    return __fdividef(num, den);
}
__device__ __forceinline__ float tanh_fast(float x) {
    float t = __expf(-2.f * x);
    return __fdividef(1.f - t, 1.f + t);
}

// ---- packed fp32x2 helpers (sm_103a FFMA2) ----
__device__ __forceinline__ u64 pk2(float x) {
    u64 r; asm("mov.b64 %0, {%1, %1};" : "=l"(r) : "f"(x)); return r;
}
__device__ __forceinline__ void f2(u64& a, u64 x, u64 y) {
    asm("fma.rn.f32x2 %0, %1, %2, %0;" : "+l"(a) : "l"(x), "l"(y));
}
__device__ __forceinline__ void upk2(u64 v, float& lo, float& hi) {
    asm("mov.b64 {%0, %1}, %2;" : "=f"(lo), "=f"(hi) : "l"(v));
}
__device__ __forceinline__ uint32_t smem_u32(const void* p) {
    uint32_t a;
    asm("{ .reg .u64 t; cvta.to.shared.u64 t, %1; cvt.u32.u64 %0, t; }"
        : "=r"(a) : "l"(p));
    return a;
}
__device__ __forceinline__ void mbar_wait_cluster(uint32_t mbar, uint32_t ph) {
    asm volatile(
        "{\n\t.reg .pred P;\n"
        "LW_%=:\n\t"
        "mbarrier.try_wait.parity.acquire.cluster.shared::cta.b64 P, [%0], %1, 0x989680;\n\t"
        "@P bra.uni LD_%=;\n\t"
        "bra.uni LW_%=;\n"
        "LD_%=:\n\t}"
        :: "r"(mbar), "r"(ph) : "memory");
}

// pack Wx -> [k][g*256+j]; fold b+theta
__global__ void pack_kernel(const float* __restrict__ W, const float* __restrict__ B,
                            const float* __restrict__ Th) {
    int idx = blockIdx.x * 256 + threadIdx.x;
    int k = idx >> 10, n = idx & 1023, g = n >> 8, j = n & 255;
    g_wxp[idx] = W[g * 131072 + k * 256 + j];
    if (idx < 1024) g_bth[idx] = B[idx] + Th[idx];
}

// ---- fp32 GEMM: 128xTN tile, 256 thr, 8x(TN/16) micro, 2 CTAs/SM forced ----
template<int TN, bool GATHER, bool RELU>
__global__ __launch_bounds__(256, 2) void gemm_kernel(
    const float* __restrict__ A, const float* __restrict__ Bm, float* __restrict__ C,
    int M, int N, int K, const float* __restrict__ bias,
    const int* __restrict__ tok, const float* __restrict__ emb)
{
    constexpr int NW = TN / 16;   // 8 or 4
    constexpr int NP = NW / 2;
    __shared__ float AsT[2][16][136];
    __shared__ float Bs [2][16][136];
    __shared__ int   toks[128];
    const int t = threadIdx.x;
    const int n0 = blockIdx.x * TN, m0 = blockIdx.y << 7;
    const int ar = t >> 1, ac8 = (t & 1) << 3;
    const int bk = t >> 4;
    const int bn = (TN == 128) ? ((t & 15) << 3) : ((t & 15) << 2);
    const int tyo = (t >> 4) << 3, txo = (t & 15) * NW;
    if (GATHER) { if (t < 128) toks[t] = tok[m0 + t]; __syncthreads(); }
    const float* arow = GATHER ? (emb + (size_t)toks[ar] * K)
                               : (A   + (size_t)(m0 + ar) * K);
    const float* brow = Bm + (size_t)bk * N + n0 + bn;

    u64 acc[8][NP];
#pragma unroll
    for (int i = 0; i < 8; i++)
#pragma unroll
        for (int j = 0; j < NP; j++) acc[i][j] = 0ull;

    float4 av0 = *(const float4*)(arow + ac8);
    float4 av1 = *(const float4*)(arow + ac8 + 4);
    float4 bv0 = *(const float4*)(brow);
    float4 bv1;
    if (TN == 128) bv1 = *(const float4*)(brow + 4);

    int s = 0, k0 = 0;
    while (true) {
        AsT[s][ac8+0][ar]=av0.x; AsT[s][ac8+1][ar]=av0.y;
        AsT[s][ac8+2][ar]=av0.z; AsT[s][ac8+3][ar]=av0.w;
        AsT[s][ac8+4][ar]=av1.x; AsT[s][ac8+5][ar]=av1.y;
        AsT[s][ac8+6][ar]=av1.z; AsT[s][ac8+7][ar]=av1.w;
        *(float4*)(&Bs[s][bk][bn]) = bv0;
        if (TN == 128) *(float4*)(&Bs[s][bk][bn+4]) = bv1;
        __syncthreads();
        k0 += 16;
        const bool more = (k0 < K);
        if (more) {
            av0 = *(const float4*)(arow + k0 + ac8);
            av1 = *(const float4*)(arow + k0 + ac8 + 4);
            bv0 = *(const float4*)(brow + (size_t)k0 * N);
            if (TN == 128) bv1 = *(const float4*)(brow + (size_t)k0 * N + 4);
        }
#pragma unroll
        for (int kk = 0; kk < 16; kk++) {
            float4 af0 = *(const float4*)(&AsT[s][kk][tyo]);
            float4 af1 = *(const float4*)(&AsT[s][kk][tyo + 4]);
            u64 a2[8];
            a2[0]=pk2(af0.x); a2[1]=pk2(af0.y); a2[2]=pk2(af0.z); a2[3]=pk2(af0.w);
            a2[4]=pk2(af1.x); a2[5]=pk2(af1.y); a2[6]=pk2(af1.z); a2[7]=pk2(af1.w);
            u64 bp[NP];
            {
                ulonglong2 bb0 = *(const ulonglong2*)(&Bs[s][kk][txo]);
                bp[0] = bb0.x; bp[1] = bb0.y;
                if (TN == 128) {
                    ulonglong2 bb1 = *(const ulonglong2*)(&Bs[s][kk][txo + 4]);
                    bp[2] = bb1.x; bp[3] = bb1.y;
                }
            }
#pragma unroll
            for (int i = 0; i < 8; i++)
#pragma unroll
                for (int j = 0; j < NP; j++) f2(acc[i][j], a2[i], bp[j]);
        }
        if (!more) break;
        s ^= 1;
    }
    float bb[NW];
#pragma unroll
    for (int j = 0; j < NW; j++) bb[j] = bias[n0 + txo + j];
#pragma unroll
    for (int i = 0; i < 8; i++) {
        float ov[NW];
#pragma unroll
        for (int j = 0; j < NP; j++) {
            float lo, hi;
            upk2(acc[i][j], lo, hi);
            ov[2*j]   = lo + bb[2*j];
            ov[2*j+1] = hi + bb[2*j+1];
        }
        if (RELU) {
#pragma unroll
            for (int j = 0; j < NW; j++) ov[j] = fmaxf(ov[j], 0.f);
        }
        float* cp = C + (size_t)(m0 + tyo + i) * N + n0 + txo;
        *(float4*)cp = make_float4(ov[0], ov[1], ov[2], ov[3]);
        if (TN == 128) *(float4*)(cp + 4) = make_float4(ov[4], ov[5], ov[6], ov[7]);
    }
}

// ---------------------------------------------------------------------------
// QLSTM recurrence (r13 proven): cluster of 8, W in registers, scalar st.async
// exchange, polynomial gate nonlinearities.
// ---------------------------------------------------------------------------
#define LSTM_SMEM_FLOATS (8*132 + 2*8*132 + 256 + 256 + 8 + 8)
__global__ __cluster_dims__(8,1,1) __launch_bounds__(256)
void lstm_kernel(const float* __restrict__ W, float* __restrict__ hseq)
{
    extern __shared__ float sm[];
    float* red  = sm;                          // [8][132]
    float* allq = red + 8*132;                 // [2][8][132]
    float* hx   = allq + 2*8*132;              // [256]
    float* cx   = hx + 256;                    // [256]
    float* wtot = cx + 256;                    // [8]
    u64*   mbar = (u64*)(wtot + 8);            // [2]

    cg::cluster_group cluster = cg::this_cluster();
    const int rank = (int)cluster.block_rank();
    const int g    = rank >> 1, half = rank & 1;
    const int b    = blockIdx.x >> 3;
    const int t    = threadIdx.x;
    const int ks   = t >> 5, jc = t & 31;
    const int lane = t & 31, w = t >> 5;

    const uint32_t allq32 = smem_u32(allq);
    const uint32_t mbar32 = smem_u32(mbar);

    if (t == 0) {
        asm volatile("mbarrier.init.shared.b64 [%0], 1;" :: "r"(mbar32) : "memory");
        asm volatile("mbarrier.init.shared.b64 [%0], 1;" :: "r"(mbar32 + 8) : "memory");
    }

    const float* gW = W + g * 131072 + 65536 + half * 128;
    ulonglong2 wr[32];
#pragma unroll
    for (int kk = 0; kk < 32; kk++)
        wr[kk] = *(const ulonglong2*)(gW + (size_t)((kk << 3) + ks) * 256 + (jc << 2));

    hx[t] = 0.f; cx[t] = 0.f;

    float pediv = __expf((float)((t >> 1) << 1) * (-9.210340371976184f / 256.f));

    uint32_t paq[8], pmb[8];
#pragma unroll
    for (int r = 0; r < 8; r++) {
        asm("mapa.shared::cluster.u32 %0, %1, %2;" : "=r"(paq[r]) : "r"(allq32), "r"(r));
        asm("mapa.shared::cluster.u32 %0, %1, %2;" : "=r"(pmb[r]) : "r"(mbar32), "r"(r));
    }

    __syncthreads();
    cluster.sync();

    const float* zxp = g_zx + (size_t)b * 256 * 1024 + g * 256 + half * 128;
    float zcur = (t < 128) ? zxp[t] : 0.f;

    for (int step = 0; step < 256; ++step) {
        const int par = step & 1;
        u64 acc01 = 0ull, acc23 = 0ull;
#pragma unroll
        for (int kk = 0; kk < 32; ++kk) {
            u64 hv2 = pk2(hx[(kk << 3) + ks]);
            f2(acc01, hv2, wr[kk].x);
            f2(acc23, hv2, wr[kk].y);
        }
        float znext = 0.f;
        if (t < 128) {
            int sn = (step < 255) ? step + 1 : step;
            znext = zxp[(size_t)sn * 1024 + t];
        }
        {
            float a0, a1, a2, a3;
            upk2(acc01, a0, a1); upk2(acc23, a2, a3);
            *(float4*)&red[ks * 132 + (jc << 2)] = make_float4(a0, a1, a2, a3);
        }
        __syncthreads();
        float p = 0.f;
        if (t < 128) {
            float z = red[t] + red[132 + t] + red[264 + t] + red[396 + t]
                    + red[528 + t] + red[660 + t] + red[792 + t] + red[924 + t]
                    + zcur;
            p = __cosf(z);
#pragma unroll
            for (int off = 1; off < 32; off <<= 1) {
                float u = __shfl_up_sync(0xffffffffu, p, off);
                if (lane >= off) p *= u;
            }
            if (lane == 31) wtot[w] = p;
        }
        zcur = znext;
        __syncthreads();
        if (t == 0) {
            asm volatile("mbarrier.arrive.expect_tx.shared.b64 _, [%0], 4096;"
                         :: "r"(mbar32 + par * 8) : "memory");
        }
        if (t < 128) {
            float pre = 1.f;
            for (int ww = 0; ww < w; ++ww) pre *= wtot[ww];
            float sv = p * pre;
            const uint32_t off4 = (uint32_t)(par * 1056 + rank * 132 + t) * 4u;
            const uint32_t svb = __float_as_uint(sv);
#pragma unroll
            for (int r = 0; r < 8; r++) {
                asm volatile(
                    "st.async.shared::cluster.mbarrier::complete_tx::bytes.b32 [%0], %1, [%2];"
                    :: "r"(paq[r] + off4), "r"(svb), "r"(pmb[r] + par * 8) : "memory");
            }
        }
        mbar_wait_cluster(mbar32 + par * 8, (uint32_t)((step >> 1) & 1));
        {
            const int sh = t >> 7, off = t & 127;
            const float* aq = allq + par * 1056;
            float qg4[4];
#pragma unroll
            for (int gg = 0; gg < 4; gg++) {
                float v = aq[(gg * 2 + sh) * 132 + off];
                if (sh) v *= aq[(gg * 2) * 132 + 127];
                qg4[gg] = v;
            }
            float f  = sigm_poly(qg4[0]);
            float ii = sigm_poly(qg4[1]);
            float gg = tanh_poly(qg4[2]);
            float oo = sigm_poly(qg4[3]);
            float cn = f * cx[t] + ii * gg;
            cx[t] = cn;
            float hn = oo * tanh_fast(cn);
            hx[t] = hn;
            if (rank == 0) {
                float ang = (float)step * pediv;
                float pe  = (t & 1) ? __cosf(ang) : __sinf(ang);
                hseq[((size_t)b * 256 + step) * 256 + t] = hn + pe;
            }
        }
        __syncthreads();
    }
    cluster.sync();
}

// fused q/k/v qproj: one warp per row, reads h once, writes 3 outputs
__global__ void qproj3_kernel(const float* __restrict__ h, const float* __restrict__ th,
                              float* __restrict__ qo, float* __restrict__ ko,
                              float* __restrict__ vo) {
    const int w = threadIdx.x >> 5, lane = threadIdx.x & 31;
    const int row = blockIdx.x * 8 + w;
    const float* hr = h + (size_t)row * 256 + lane * 8;
    float4 h0 = *(const float4*)hr, h1 = *(const float4*)(hr + 4);
    float* outs[3] = {qo, ko, vo};
#pragma unroll
    for (int c = 0; c < 3; c++) {
        const float* tr = th + c * 256 + lane * 8;
        float4 t0 = *(const float4*)tr, t1 = *(const float4*)(tr + 4);
        float p[8], run;
        run  = __cosf(h0.x+t0.x); p[0]=run;  run *= __cosf(h0.y+t0.y); p[1]=run;
        run *= __cosf(h0.z+t0.z); p[2]=run;  run *= __cosf(h0.w+t0.w); p[3]=run;
        run *= __cosf(h1.x+t1.x); p[4]=run;  run *= __cosf(h1.y+t1.y); p[5]=run;
        run *= __cosf(h1.z+t1.z); p[6]=run;  run *= __cosf(h1.w+t1.w); p[7]=run;
        float incl = run;
#pragma unroll
        for (int off = 1; off < 32; off <<= 1) {
            float u = __shfl_up_sync(0xffffffffu, incl, off);
            if (lane >= off) incl *= u;
        }
        float ex = __shfl_up_sync(0xffffffffu, incl, 1);
        if (lane == 0) ex = 1.f;
        float* o = outs[c] + (size_t)row * 256 + lane * 8;
        *(float4*)o     = make_float4(ex*p[0], ex*p[1], ex*p[2], ex*p[3]);
        *(float4*)(o+4) = make_float4(ex*p[4], ex*p[5], ex*p[6], ex*p[7]);
    }
}

// fused attention, 2-row blocking per warp, FFMA2 inner products
#define ATTN_SMEM (36864 + 33280 + 16384 + 2048)
__global__ __launch_bounds__(256) void attn_kernel(const float* __restrict__ Q,
    const float* __restrict__ K, const float* __restrict__ V, float* __restrict__ O)
{
    extern __shared__ float sm[];
    float* kh = sm;               // [256][36]
    float* vt = sm + 256 * 36;    // [32][260]
    float* ps = vt + 32 * 260;    // [8][2][256]
    float* qs = ps + 8 * 512;     // [8][64]
    const int b = blockIdx.x >> 3, hh = blockIdx.x & 7;
    const int t = threadIdx.x, w = t >> 5, lane = t & 31;
    const size_t base = ((size_t)b * 256) * 256 + hh * 32;
    for (int idx = t; idx < 8192; idx += 256) {
        int kr = idx >> 5, d = idx & 31;
        size_t go = base + (size_t)kr * 256 + d;
        kh[kr * 36 + d]  = K[go];
        vt[d * 260 + kr] = V[go];
    }
    __syncthreads();
    float* qsw = qs + w * 64;
    float* ps0 = ps + w * 512;
    float* ps1 = ps0 + 256;
    for (int i = 0; i < 16; i++) {
        const int r0 = w + 8 * i, r1 = r0 + 128;
        qsw[lane]      = Q[base + (size_t)r0 * 256 + lane];
        qsw[32 + lane] = Q[base + (size_t)r1 * 256 + lane];
        __syncwarp();
        u64 qa[16], qb[16];
        {
            const ulonglong2* qp = (const ulonglong2*)qsw;
#pragma unroll
            for (int u = 0; u < 8; u++) {
                ulonglong2 v0 = qp[u];     qa[2*u] = v0.x; qa[2*u+1] = v0.y;
                ulonglong2 v1 = qp[u + 8]; qb[2*u] = v1.x; qb[2*u+1] = v1.y;
            }
        }
        float s0[8], s1[8];
#pragma unroll
        for (int c = 0; c < 8; c++) {
            const ulonglong2* kp = (const ulonglong2*)(kh + (c * 32 + lane) * 36);
            u64 a0 = 0ull, a1 = 0ull;
#pragma unroll
            for (int u = 0; u < 8; u++) {
                ulonglong2 kv = kp[u];
                f2(a0, qa[2*u], kv.x); f2(a0, qa[2*u+1], kv.y);
                f2(a1, qb[2*u], kv.x); f2(a1, qb[2*u+1], kv.y);
            }
            float lo, hi;
            upk2(a0, lo, hi); s0[c] = (lo + hi) * 0.17677669529663689f;
            upk2(a1, lo, hi); s1[c] = (lo + hi) * 0.17677669529663689f;
        }
        float m0 = s0[0], m1 = s1[0];
#pragma unroll
        for (int c = 1; c < 8; c++) { m0 = fmaxf(m0, s0[c]); m1 = fmaxf(m1, s1[c]); }
#pragma unroll
        for (int off = 16; off; off >>= 1) {
            m0 = fmaxf(m0, __shfl_xor_sync(0xffffffffu, m0, off));
            m1 = fmaxf(m1, __shfl_xor_sync(0xffffffffu, m1, off));
        }
        float sum0 = 0.f, sum1 = 0.f;
#pragma unroll
        for (int c = 0; c < 8; c++) {
            s0[c] = __expf(s0[c] - m0); sum0 += s0[c];
            s1[c] = __expf(s1[c] - m1); sum1 += s1[c];
        }
#pragma unroll
        for (int off = 16; off; off >>= 1) {
            sum0 += __shfl_xor_sync(0xffffffffu, sum0, off);
            sum1 += __shfl_xor_sync(0xffffffffu, sum1, off);
        }
#pragma unroll
        for (int c = 0; c < 8; c++) {
            ps0[c * 32 + lane] = s0[c];
            ps1[c * 32 + lane] = s1[c];
        }
        __syncwarp();
        u64 a0 = 0ull, a1 = 0ull;
        const ulonglong2* pp0 = (const ulonglong2*)ps0;
        const ulonglong2* pp1 = (const ulonglong2*)ps1;
        const ulonglong2* vp  = (const ulonglong2*)(vt + lane * 260);
#pragma unroll
        for (int k8 = 0; k8 < 64; k8++) {
            ulonglong2 vv = vp[k8];
            ulonglong2 p0 = pp0[k8];
            ulonglong2 p1 = pp1[k8];
            f2(a0, p0.x, vv.x); f2(a0, p0.y, vv.y);
            f2(a1, p1.x, vv.x); f2(a1, p1.y, vv.y);
        }
        float lo, hi;
        upk2(a0, lo, hi); O[base + (size_t)r0 * 256 + lane] = (lo + hi) / sum0;
        upk2(a1, lo, hi); O[base + (size_t)r1 * 256 + lane] = (lo + hi) / sum1;
        __syncwarp();
    }
}

// residual add + LayerNorm; optionally fused qproj of the LN output (NQ outputs)
template<int NQ>
__global__ void resid_ln_kernel(float* __restrict__ h, const float* __restrict__ d,
                                const float* __restrict__ gw, const float* __restrict__ bw,
                                const float* __restrict__ th,
                                float* __restrict__ q0, float* __restrict__ q1,
                                float* __restrict__ q2) {
    const int row = blockIdx.x, j = threadIdx.x, w = j >> 5, lane = j & 31;
    __shared__ float ssum[8], ssq[8], wt[3][8];
    size_t off = (size_t)row * 256 + j;
    float v = h[off] + d[off];
    float s = v, s2 = v * v;
#pragma unroll
    for (int o = 16; o; o >>= 1) {
        s  += __shfl_xor_sync(0xffffffffu, s, o);
        s2 += __shfl_xor_sync(0xffffffffu, s2, o);
    }
    if (lane == 0) { ssum[w] = s; ssq[w] = s2; }
    __syncthreads();
    if (j == 0) {
        float S = 0.f, S2 = 0.f;
        for (int i = 0; i < 8; i++) { S += ssum[i]; S2 += ssq[i]; }
        ssum[0] = S; ssq[0] = S2;
    }
    __syncthreads();
    float mean = ssum[0] * (1.f/256.f);
    float var  = ssq[0]  * (1.f/256.f) - mean * mean;
    float nv = (v - mean) * rsqrtf(var + 1e-5f) * gw[j] + bw[j];
    h[off] = nv;
    if (NQ > 0) {
        float* outs[3] = {q0, q1, q2};
#pragma unroll
        for (int c = 0; c < NQ; c++) {
            float p = __cosf(nv + th[c * 256 + j]);
#pragma unroll
            for (int o = 1; o < 32; o <<= 1) {
                float u = __shfl_up_sync(0xffffffffu, p, o);
                if (lane >= o) p *= u;
            }
            if (lane == 31) wt[c][w] = p;
            __syncthreads();
            float pre = 1.f;
            for (int ww = 0; ww < w; ++ww) pre *= wt[c][ww];
            outs[c][off] = p * pre;
        }
    }
}

__global__ void pool_cls_kernel(const float* __restrict__ h, const float* __restrict__ Wc,
                                const float* __restrict__ bc, float* __restrict__ out) {
    __shared__ float pooled[256];
    const int b = blockIdx.x, e = threadIdx.x;
    float s = 0.f;
    for (int tt = 0; tt < 256; ++tt) s += h[((size_t)b * 256 + tt) * 256 + e];
    pooled[e] = s * (1.f/256.f);
    __syncthreads();
    if (e < 4) {
        float a = bc[e];
        for (int i = 0; i < 256; i++) a = fmaf(pooled[i], Wc[i * 4 + e], a);
        out[b * 4 + e] = a;
    }
}

extern "C" void kernel_launch(void* const* d_in, const int* in_sizes, int n_in,
                              void* d_out, int out_size)
{
    const int*   x      = (const int*)  d_in[0];
    const float* tokemb = (const float*)d_in[1];
    const float* lstmW  = (const float*)d_in[2];
    const float* lstmB  = (const float*)d_in[3];
    const float* lstmTh = (const float*)d_in[4];
    const float* ln1g   = (const float*)d_in[5];
    const float* ln1b   = (const float*)d_in[6];
    const float* ln2g   = (const float*)d_in[7];
    const float* ln2b   = (const float*)d_in[8];
    const float* qkvTh  = (const float*)d_in[9];
    const float* combW  = (const float*)d_in[10];
    const float* combB  = (const float*)d_in[11];
    const float* ffnTh  = (const float*)d_in[12];
    const float* lin1W  = (const float*)d_in[13];
    const float* lin1B  = (const float*)d_in[14];
    const float* lin2W  = (const float*)d_in[15];
    const float* lin2B  = (const float*)d_in[16];
    const float* clsW   = (const float*)d_in[17];
    const float* clsB   = (const float*)d_in[18];
    float* out = (float*)d_out;

    float *p_zx,*p_wxp,*p_bth,*p_h,*p_q,*p_k,*p_v,*p_at,*p_ffq,*p_t1,*p_t2;
    cudaGetSymbolAddress((void**)&p_zx,  g_zx);
    cudaGetSymbolAddress((void**)&p_wxp, g_wxp);
    cudaGetSymbolAddress((void**)&p_bth, g_bth);
    cudaGetSymbolAddress((void**)&p_h,   g_h);
    cudaGetSymbolAddress((void**)&p_q,   g_q);
    cudaGetSymbolAddress((void**)&p_k,   g_k);
    cudaGetSymbolAddress((void**)&p_v,   g_v);
    cudaGetSymbolAddress((void**)&p_at,  g_at);
    cudaGetSymbolAddress((void**)&p_ffq, g_ffq);
    cudaGetSymbolAddress((void**)&p_t1,  g_t1);
    cudaGetSymbolAddress((void**)&p_t2,  g_t2);

    cudaFuncSetAttribute(attn_kernel, cudaFuncAttributeMaxDynamicSharedMemorySize, ATTN_SMEM);
    cudaFuncSetAttribute(lstm_kernel, cudaFuncAttributeMaxDynamicSharedMemorySize,
                         LSTM_SMEM_FLOATS * 4);

    pack_kernel<<<1024, 256>>>(lstmW, lstmB, lstmTh);
    gemm_kernel<128, true, false><<<dim3(8, 32), 256>>>(
        nullptr, p_wxp, p_zx, ROWS, 1024, 256, p_bth, x, tokemb);
    lstm_kernel<<<128, 256, LSTM_SMEM_FLOATS * 4>>>(lstmW, p_h);

    // ---- layer 0 ----
    qproj3_kernel<<<ROWS/8, 256>>>(p_h, qkvTh, p_q, p_k, p_v);
    attn_kernel<<<Bb*8, 256, ATTN_SMEM>>>(p_q, p_k, p_v, p_at);
    gemm_kernel<64, false, false><<<dim3(4, 32), 256>>>(
        p_at, combW, p_t2, ROWS, 256, 256, combB, nullptr, nullptr);
    resid_ln_kernel<1><<<ROWS, 256>>>(p_h, p_t2, ln1g, ln1b, ffnTh,
                                      p_ffq, nullptr, nullptr);
    gemm_kernel<128, false, true><<<dim3(8, 32), 256>>>(
        p_ffq, lin1W, p_t1, ROWS, 1024, 256, lin1B, nullptr, nullptr);
    gemm_kernel<64, false, false><<<dim3(4, 32), 256>>>(
        p_t1, lin2W, p_t2, ROWS, 256, 1024, lin2B, nullptr, nullptr);
    resid_ln_kernel<3><<<ROWS, 256>>>(p_h, p_t2, ln2g, ln2b, qkvTh + 3*256,
                                      p_q, p_k, p_v);

    // ---- layer 1 ----
    attn_kernel<<<Bb*8, 256, ATTN_SMEM>>>(p_q, p_k, p_v, p_at);
    gemm_kernel<64, false, false><<<dim3(4, 32), 256>>>(
        p_at, combW + 256*256, p_t2, ROWS, 256, 256, combB + 256, nullptr, nullptr);
    resid_ln_kernel<1><<<ROWS, 256>>>(p_h, p_t2, ln1g + 256, ln1b + 256,
                                      ffnTh + 256, p_ffq, nullptr, nullptr);
    gemm_kernel<128, false, true><<<dim3(8, 32), 256>>>(
        p_ffq, lin1W + 256*1024, p_t1, ROWS, 1024, 256, lin1B + 1024,
        nullptr, nullptr);
    gemm_kernel<64, false, false><<<dim3(4, 32), 256>>>(
        p_t1, lin2W + 1024*256, p_t2, ROWS, 256, 1024, lin2B + 256,
        nullptr, nullptr);
    resid_ln_kernel<0><<<ROWS, 256>>>(p_h, p_t2, ln2g + 256, ln2b + 256,
                                      nullptr, nullptr, nullptr, nullptr);

    pool_cls_kernel<<<Bb, 256>>>(p_h, clsW, clsB, out);
}

// round 15
// speedup vs baseline: 2.2302x; 1.0165x over previous
#include <cuda_runtime.h>
#include <math.h>
#include <cooperative_groups.h>
namespace cg = cooperative_groups;

#define Bb 16
#define Ss 256
#define Ee 256
#define ROWS (Bb*Ss)
#define FFNf 1024

typedef unsigned long long u64;

__device__ float g_zx [ROWS*1024];
__device__ float g_wxp[256*1024];
__device__ float g_bth[1024];
__device__ float g_h  [ROWS*Ee];
__device__ float g_q  [ROWS*Ee];
__device__ float g_k  [ROWS*Ee];
__device__ float g_v  [ROWS*Ee];
__device__ float g_at [ROWS*Ee];
__device__ float g_ffq[ROWS*Ee];
__device__ float g_t1 [ROWS*FFNf];
__device__ float g_t2 [ROWS*Ee];

__device__ __forceinline__ float sigm_poly(float x) {
    float x2 = x * x;
    float p = fmaf(x2, 2.13569388e-5f, -2.10813492e-4f);
    p = fmaf(x2, p, 2.08333333e-3f);
    p = fmaf(x2, p, -2.08333333e-2f);
    p = fmaf(x2, p, 0.25f);
    return fmaf(x, p, 0.5f);
}
// tanh on [-1,1]: Pade [5/4], 1 MUFU.
__device__ __forceinline__ float tanh_poly(float x) {
    float x2 = x * x;
    float num = x * fmaf(x2, fmaf(x2, 1.f, 105.f), 945.f);
    float den = fmaf(x2, fmaf(x2, 15.f, 420.f), 945.f);
    return __fdividef(num, den);
}
// tanh on [-3,3]: Pade [7/6], |err| < 2e-6, 1 MUFU (was exp-based, 2 MUFU).
__device__ __forceinline__ float tanh_pade(float x) {
    float x2 = x * x;
    float num = x * fmaf(x2, fmaf(x2, fmaf(x2, 1.f, 378.f), 17325.f), 135135.f);
    float den = fmaf(x2, fmaf(x2, fmaf(x2, 28.f, 3150.f), 62370.f), 135135.f);
    return __fdividef(num, den);
}

// ---- packed fp32x2 helpers (sm_103a FFMA2) ----
__device__ __forceinline__ u64 pk2(float x) {
    u64 r; asm("mov.b64 %0, {%1, %1};" : "=l"(r) : "f"(x)); return r;
}
__device__ __forceinline__ void f2(u64& a, u64 x, u64 y) {
    asm("fma.rn.f32x2 %0, %1, %2, %0;" : "+l"(a) : "l"(x), "l"(y));
}
__device__ __forceinline__ void upk2(u64 v, float& lo, float& hi) {
    asm("mov.b64 {%0, %1}, %2;" : "=f"(lo), "=f"(hi) : "l"(v));
}
__device__ __forceinline__ uint32_t smem_u32(const void* p) {
    uint32_t a;
    asm("{ .reg .u64 t; cvta.to.shared.u64 t, %1; cvt.u32.u64 %0, t; }"
        : "=r"(a) : "l"(p));
    return a;
}
__device__ __forceinline__ void mbar_wait_cluster(uint32_t mbar, uint32_t ph) {
    asm volatile(
        "{\n\t.reg .pred P;\n"
        "LW_%=:\n\t"
        "mbarrier.try_wait.parity.acquire.cluster.shared::cta.b64 P, [%0], %1, 0x989680;\n\t"
        "@P bra.uni LD_%=;\n\t"
        "bra.uni LW_%=;\n"
        "LD_%=:\n\t}"
        :: "r"(mbar), "r"(ph) : "memory");
}

// pack Wx -> [k][g*256+j]; fold b+theta
__global__ void pack_kernel(const float* __restrict__ W, const float* __restrict__ B,
                            const float* __restrict__ Th) {
    int idx = blockIdx.x * 256 + threadIdx.x;
    int k = idx >> 10, n = idx & 1023, g = n >> 8, j = n & 255;
    g_wxp[idx] = W[g * 131072 + k * 256 + j];
    if (idx < 1024) g_bth[idx] = B[idx] + Th[idx];
}

// ---- fp32 GEMM: 128xTN tile, 256 thr, 8x(TN/16) micro, 2 CTAs/SM forced ----
template<int TN, bool GATHER, bool RELU>
__global__ __launch_bounds__(256, 2) void gemm_kernel(
    const float* __restrict__ A, const float* __restrict__ Bm, float* __restrict__ C,
    int M, int N, int K, const float* __restrict__ bias,
    const int* __restrict__ tok, const float* __restrict__ emb)
{
    constexpr int NW = TN / 16;
    constexpr int NP = NW / 2;
    __shared__ float AsT[2][16][136];
    __shared__ float Bs [2][16][136];
    __shared__ int   toks[128];
    const int t = threadIdx.x;
    const int n0 = blockIdx.x * TN, m0 = blockIdx.y << 7;
    const int ar = t >> 1, ac8 = (t & 1) << 3;
    const int bk = t >> 4;
    const int bn = (TN == 128) ? ((t & 15) << 3) : ((t & 15) << 2);
    const int tyo = (t >> 4) << 3, txo = (t & 15) * NW;
    if (GATHER) { if (t < 128) toks[t] = tok[m0 + t]; __syncthreads(); }
    const float* arow = GATHER ? (emb + (size_t)toks[ar] * K)
                               : (A   + (size_t)(m0 + ar) * K);
    const float* brow = Bm + (size_t)bk * N + n0 + bn;

    u64 acc[8][NP];
#pragma unroll
    for (int i = 0; i < 8; i++)
#pragma unroll
        for (int j = 0; j < NP; j++) acc[i][j] = 0ull;

    float4 av0 = *(const float4*)(arow + ac8);
    float4 av1 = *(const float4*)(arow + ac8 + 4);
    float4 bv0 = *(const float4*)(brow);
    float4 bv1;
    if (TN == 128) bv1 = *(const float4*)(brow + 4);

    int s = 0, k0 = 0;
    while (true) {
        AsT[s][ac8+0][ar]=av0.x; AsT[s][ac8+1][ar]=av0.y;
        AsT[s][ac8+2][ar]=av0.z; AsT[s][ac8+3][ar]=av0.w;
        AsT[s][ac8+4][ar]=av1.x; AsT[s][ac8+5][ar]=av1.y;
        AsT[s][ac8+6][ar]=av1.z; AsT[s][ac8+7][ar]=av1.w;
        *(float4*)(&Bs[s][bk][bn]) = bv0;
        if (TN == 128) *(float4*)(&Bs[s][bk][bn+4]) = bv1;
        __syncthreads();
        k0 += 16;
        const bool more = (k0 < K);
        if (more) {
            av0 = *(const float4*)(arow + k0 + ac8);
            av1 = *(const float4*)(arow + k0 + ac8 + 4);
            bv0 = *(const float4*)(brow + (size_t)k0 * N);
            if (TN == 128) bv1 = *(const float4*)(brow + (size_t)k0 * N + 4);
        }
#pragma unroll
        for (int kk = 0; kk < 16; kk++) {
            float4 af0 = *(const float4*)(&AsT[s][kk][tyo]);
            float4 af1 = *(const float4*)(&AsT[s][kk][tyo + 4]);
            u64 a2[8];
            a2[0]=pk2(af0.x); a2[1]=pk2(af0.y); a2[2]=pk2(af0.z); a2[3]=pk2(af0.w);
            a2[4]=pk2(af1.x); a2[5]=pk2(af1.y); a2[6]=pk2(af1.z); a2[7]=pk2(af1.w);
            u64 bp[NP];
            {
                ulonglong2 bb0 = *(const ulonglong2*)(&Bs[s][kk][txo]);
                bp[0] = bb0.x; bp[1] = bb0.y;
                if (TN == 128) {
                    ulonglong2 bb1 = *(const ulonglong2*)(&Bs[s][kk][txo + 4]);
                    bp[2] = bb1.x; bp[3] = bb1.y;
                }
            }
#pragma unroll
            for (int i = 0; i < 8; i++)
#pragma unroll
                for (int j = 0; j < NP; j++) f2(acc[i][j], a2[i], bp[j]);
        }
        if (!more) break;
        s ^= 1;
    }
    float bb[NW];
#pragma unroll
    for (int j = 0; j < NW; j++) bb[j] = bias[n0 + txo + j];
#pragma unroll
    for (int i = 0; i < 8; i++) {
        float ov[NW];
#pragma unroll
        for (int j = 0; j < NP; j++) {
            float lo, hi;
            upk2(acc[i][j], lo, hi);
            ov[2*j]   = lo + bb[2*j];
            ov[2*j+1] = hi + bb[2*j+1];
        }
        if (RELU) {
#pragma unroll
            for (int j = 0; j < NW; j++) ov[j] = fmaxf(ov[j], 0.f);
        }
        float* cp = C + (size_t)(m0 + tyo + i) * N + n0 + txo;
        *(float4*)cp = make_float4(ov[0], ov[1], ov[2], ov[3]);
        if (TN == 128) *(float4*)(cp + 4) = make_float4(ov[4], ov[5], ov[6], ov[7]);
    }
}

// ---------------------------------------------------------------------------
// QLSTM recurrence: cluster of 8, W in registers, scalar st.async exchange,
// polynomial gates (tanh(cn) now Pade[7/6], PE via incremental rotation).
// ---------------------------------------------------------------------------
#define LSTM_SMEM_FLOATS (8*132 + 2*8*132 + 256 + 256 + 8 + 8)
__global__ __cluster_dims__(8,1,1) __launch_bounds__(256)
void lstm_kernel(const float* __restrict__ W, float* __restrict__ hseq)
{
    extern __shared__ float sm[];
    float* red  = sm;                          // [8][132]
    float* allq = red + 8*132;                 // [2][8][132]
    float* hx   = allq + 2*8*132;              // [256]
    float* cx   = hx + 256;                    // [256]
    float* wtot = cx + 256;                    // [8]
    u64*   mbar = (u64*)(wtot + 8);            // [2]

    cg::cluster_group cluster = cg::this_cluster();
    const int rank = (int)cluster.block_rank();
    const int g    = rank >> 1, half = rank & 1;
    const int b    = blockIdx.x >> 3;
    const int t    = threadIdx.x;
    const int ks   = t >> 5, jc = t & 31;
    const int lane = t & 31, w = t >> 5;

    const uint32_t allq32 = smem_u32(allq);
    const uint32_t mbar32 = smem_u32(mbar);

    if (t == 0) {
        asm volatile("mbarrier.init.shared.b64 [%0], 1;" :: "r"(mbar32) : "memory");
        asm volatile("mbarrier.init.shared.b64 [%0], 1;" :: "r"(mbar32 + 8) : "memory");
    }

    const float* gW = W + g * 131072 + 65536 + half * 128;
    ulonglong2 wr[32];
#pragma unroll
    for (int kk = 0; kk < 32; kk++)
        wr[kk] = *(const ulonglong2*)(gW + (size_t)((kk << 3) + ks) * 256 + (jc << 2));

    hx[t] = 0.f; cx[t] = 0.f;

    // PE incremental rotation state: (sin, cos)(step * d)
    float ped = __expf((float)((t >> 1) << 1) * (-9.210340371976184f / 256.f));
    float psd = __sinf(ped), pcd = __cosf(ped);
    float ps = 0.f, pc = 1.f;

    uint32_t paq[8], pmb[8];
#pragma unroll
    for (int r = 0; r < 8; r++) {
        asm("mapa.shared::cluster.u32 %0, %1, %2;" : "=r"(paq[r]) : "r"(allq32), "r"(r));
        asm("mapa.shared::cluster.u32 %0, %1, %2;" : "=r"(pmb[r]) : "r"(mbar32), "r"(r));
    }

    __syncthreads();
    cluster.sync();

    const float* zxp = g_zx + (size_t)b * 256 * 1024 + g * 256 + half * 128;
    float zcur = (t < 128) ? zxp[t] : 0.f;

    for (int step = 0; step < 256; ++step) {
        const int par = step & 1;
        u64 acc01 = 0ull, acc23 = 0ull;
#pragma unroll
        for (int kk = 0; kk < 32; ++kk) {
            u64 hv2 = pk2(hx[(kk << 3) + ks]);
            f2(acc01, hv2, wr[kk].x);
            f2(acc23, hv2, wr[kk].y);
        }
        float znext = 0.f;
        if (t < 128) {
            int sn = (step < 255) ? step + 1 : step;
            znext = zxp[(size_t)sn * 1024 + t];
        }
        {
            float a0, a1, a2, a3;
            upk2(acc01, a0, a1); upk2(acc23, a2, a3);
            *(float4*)&red[ks * 132 + (jc << 2)] = make_float4(a0, a1, a2, a3);
        }
        __syncthreads();
        float p = 0.f;
        if (t < 128) {
            float z = red[t] + red[132 + t] + red[264 + t] + red[396 + t]
                    + red[528 + t] + red[660 + t] + red[792 + t] + red[924 + t]
                    + zcur;
            p = __cosf(z);
#pragma unroll
            for (int off = 1; off < 32; off <<= 1) {
                float u = __shfl_up_sync(0xffffffffu, p, off);
                if (lane >= off) p *= u;
            }
            if (lane == 31) wtot[w] = p;
        }
        zcur = znext;
        __syncthreads();
        if (t == 0) {
            asm volatile("mbarrier.arrive.expect_tx.shared.b64 _, [%0], 4096;"
                         :: "r"(mbar32 + par * 8) : "memory");
        }
        if (t < 128) {
            float pre = 1.f;
            for (int ww = 0; ww < w; ++ww) pre *= wtot[ww];
            float sv = p * pre;
            const uint32_t off4 = (uint32_t)(par * 1056 + rank * 132 + t) * 4u;
            const uint32_t svb = __float_as_uint(sv);
#pragma unroll
            for (int r = 0; r < 8; r++) {
                asm volatile(
                    "st.async.shared::cluster.mbarrier::complete_tx::bytes.b32 [%0], %1, [%2];"
                    :: "r"(paq[r] + off4), "r"(svb), "r"(pmb[r] + par * 8) : "memory");
            }
        }
        mbar_wait_cluster(mbar32 + par * 8, (uint32_t)((step >> 1) & 1));
        {
            const int sh = t >> 7, off = t & 127;
            const float* aq = allq + par * 1056;
            float qg4[4];
#pragma unroll
            for (int gg = 0; gg < 4; gg++) {
                float v = aq[(gg * 2 + sh) * 132 + off];
                if (sh) v *= aq[(gg * 2) * 132 + 127];
                qg4[gg] = v;
            }
            float f  = sigm_poly(qg4[0]);
            float ii = sigm_poly(qg4[1]);
            float gg = tanh_poly(qg4[2]);
            float oo = sigm_poly(qg4[3]);
            float cn = f * cx[t] + ii * gg;
            cx[t] = cn;
            float hn = oo * tanh_pade(cn);
            hx[t] = hn;
            if (rank == 0) {
                float pe = (t & 1) ? pc : ps;
                hseq[((size_t)b * 256 + step) * 256 + t] = hn + pe;
            }
            // rotate PE state (4 FMA, no MUFU)
            float ns = fmaf(ps, pcd,  pc * psd);
            float nc = fmaf(pc, pcd, -ps * psd);
            ps = ns; pc = nc;
        }
        __syncthreads();
    }
    cluster.sync();
}

// fused q/k/v qproj: one warp per row, reads h once, writes 3 outputs
__global__ void qproj3_kernel(const float* __restrict__ h, const float* __restrict__ th,
                              float* __restrict__ qo, float* __restrict__ ko,
                              float* __restrict__ vo) {
    const int w = threadIdx.x >> 5, lane = threadIdx.x & 31;
    const int row = blockIdx.x * 8 + w;
    const float* hr = h + (size_t)row * 256 + lane * 8;
    float4 h0 = *(const float4*)hr, h1 = *(const float4*)(hr + 4);
    float* outs[3] = {qo, ko, vo};
#pragma unroll
    for (int c = 0; c < 3; c++) {
        const float* tr = th + c * 256 + lane * 8;
        float4 t0 = *(const float4*)tr, t1 = *(const float4*)(tr + 4);
        float p[8], run;
        run  = __cosf(h0.x+t0.x); p[0]=run;  run *= __cosf(h0.y+t0.y); p[1]=run;
        run *= __cosf(h0.z+t0.z); p[2]=run;  run *= __cosf(h0.w+t0.w); p[3]=run;
        run *= __cosf(h1.x+t1.x); p[4]=run;  run *= __cosf(h1.y+t1.y); p[5]=run;
        run *= __cosf(h1.z+t1.z); p[6]=run;  run *= __cosf(h1.w+t1.w); p[7]=run;
        float incl = run;
#pragma unroll
        for (int off = 1; off < 32; off <<= 1) {
            float u = __shfl_up_sync(0xffffffffu, incl, off);
            if (lane >= off) incl *= u;
        }
        float ex = __shfl_up_sync(0xffffffffu, incl, 1);
        if (lane == 0) ex = 1.f;
        float* o = outs[c] + (size_t)row * 256 + lane * 8;
        *(float4*)o     = make_float4(ex*p[0], ex*p[1], ex*p[2], ex*p[3]);
        *(float4*)(o+4) = make_float4(ex*p[4], ex*p[5], ex*p[6], ex*p[7]);
    }
}

// fused attention, 2-row blocking per warp, FFMA2 inner products
#define ATTN_SMEM (36864 + 33280 + 16384 + 2048)
__global__ __launch_bounds__(256) void attn_kernel(const float* __restrict__ Q,
    const float* __restrict__ K, const float* __restrict__ V, float* __restrict__ O)
{
    extern __shared__ float sm[];
    float* kh = sm;               // [256][36]
    float* vt = sm + 256 * 36;    // [32][260]
    float* ps = vt + 32 * 260;    // [8][2][256]
    float* qs = ps + 8 * 512;     // [8][64]
    const int b = blockIdx.x >> 3, hh = blockIdx.x & 7;
    const int t = threadIdx.x, w = t >> 5, lane = t & 31;
    const size_t base = ((size_t)b * 256) * 256 + hh * 32;
    for (int idx = t; idx < 8192; idx += 256) {
        int kr = idx >> 5, d = idx & 31;
        size_t go = base + (size_t)kr * 256 + d;
        kh[kr * 36 + d]  = K[go];
        vt[d * 260 + kr] = V[go];
    }
    __syncthreads();
    float* qsw = qs + w * 64;
    float* ps0 = ps + w * 512;
    float* ps1 = ps0 + 256;
    for (int i = 0; i < 16; i++) {
        const int r0 = w + 8 * i, r1 = r0 + 128;
        qsw[lane]      = Q[base + (size_t)r0 * 256 + lane];
        qsw[32 + lane] = Q[base + (size_t)r1 * 256 + lane];
        __syncwarp();
        u64 qa[16], qb[16];
        {
            const ulonglong2* qp = (const ulonglong2*)qsw;
#pragma unroll
            for (int u = 0; u < 8; u++) {
                ulonglong2 v0 = qp[u];     qa[2*u] = v0.x; qa[2*u+1] = v0.y;
                ulonglong2 v1 = qp[u + 8]; qb[2*u] = v1.x; qb[2*u+1] = v1.y;
            }
        }
        float s0[8], s1[8];
#pragma unroll
        for (int c = 0; c < 8; c++) {
            const ulonglong2* kp = (const ulonglong2*)(kh + (c * 32 + lane) * 36);
            u64 a0 = 0ull, a1 = 0ull;
#pragma unroll
            for (int u = 0; u < 8; u++) {
                ulonglong2 kv = kp[u];
                f2(a0, qa[2*u], kv.x); f2(a0, qa[2*u+1], kv.y);
                f2(a1, qb[2*u], kv.x); f2(a1, qb[2*u+1], kv.y);
            }
            float lo, hi;
            upk2(a0, lo, hi); s0[c] = (lo + hi) * 0.17677669529663689f;
            upk2(a1, lo, hi); s1[c] = (lo + hi) * 0.17677669529663689f;
        }
        float m0 = s0[0], m1 = s1[0];
#pragma unroll
        for (int c = 1; c < 8; c++) { m0 = fmaxf(m0, s0[c]); m1 = fmaxf(m1, s1[c]); }
#pragma unroll
        for (int off = 16; off; off >>= 1) {
            m0 = fmaxf(m0, __shfl_xor_sync(0xffffffffu, m0, off));
            m1 = fmaxf(m1, __shfl_xor_sync(0xffffffffu, m1, off));
        }
        float sum0 = 0.f, sum1 = 0.f;
#pragma unroll
        for (int c = 0; c < 8; c++) {
            s0[c] = __expf(s0[c] - m0); sum0 += s0[c];
            s1[c] = __expf(s1[c] - m1); sum1 += s1[c];
        }
#pragma unroll
        for (int off = 16; off; off >>= 1) {
            sum0 += __shfl_xor_sync(0xffffffffu, sum0, off);
            sum1 += __shfl_xor_sync(0xffffffffu, sum1, off);
        }
#pragma unroll
        for (int c = 0; c < 8; c++) {
            ps0[c * 32 + lane] = s0[c];
            ps1[c * 32 + lane] = s1[c];
        }
        __syncwarp();
        u64 a0 = 0ull, a1 = 0ull;
        const ulonglong2* pp0 = (const ulonglong2*)ps0;
        const ulonglong2* pp1 = (const ulonglong2*)ps1;
        const ulonglong2* vp  = (const ulonglong2*)(vt + lane * 260);
#pragma unroll
        for (int k8 = 0; k8 < 64; k8++) {
            ulonglong2 vv = vp[k8];
            ulonglong2 p0 = pp0[k8];
            ulonglong2 p1 = pp1[k8];
            f2(a0, p0.x, vv.x); f2(a0, p0.y, vv.y);
            f2(a1, p1.x, vv.x); f2(a1, p1.y, vv.y);
        }
        float lo, hi;
        upk2(a0, lo, hi); O[base + (size_t)r0 * 256 + lane] = (lo + hi) / sum0;
        upk2(a1, lo, hi); O[base + (size_t)r1 * 256 + lane] = (lo + hi) / sum1;
        __syncwarp();
    }
}

// residual add + LayerNorm; optionally fused qproj of the LN output (NQ outputs)
template<int NQ>
__global__ void resid_ln_kernel(float* __restrict__ h, const float* __restrict__ d,
                                const float* __restrict__ gw, const float* __restrict__ bw,
                                const float* __restrict__ th,
                                float* __restrict__ q0, float* __restrict__ q1,
                                float* __restrict__ q2) {
    const int row = blockIdx.x, j = threadIdx.x, w = j >> 5, lane = j & 31;
    __shared__ float ssum[8], ssq[8], wt[3][8];
    size_t off = (size_t)row * 256 + j;
    float v = h[off] + d[off];
    float s = v, s2 = v * v;
#pragma unroll
    for (int o = 16; o; o >>= 1) {
        s  += __shfl_xor_sync(0xffffffffu, s, o);
        s2 += __shfl_xor_sync(0xffffffffu, s2, o);
    }
    if (lane == 0) { ssum[w] = s; ssq[w] = s2; }
    __syncthreads();
    if (j == 0) {
        float S = 0.f, S2 = 0.f;
        for (int i = 0; i < 8; i++) { S += ssum[i]; S2 += ssq[i]; }
        ssum[0] = S; ssq[0] = S2;
    }
    __syncthreads();
    float mean = ssum[0] * (1.f/256.f);
    float var  = ssq[0]  * (1.f/256.f) - mean * mean;
    float nv = (v - mean) * rsqrtf(var + 1e-5f) * gw[j] + bw[j];
    h[off] = nv;
    if (NQ > 0) {
        float* outs[3] = {q0, q1, q2};
#pragma unroll
        for (int c = 0; c < NQ; c++) {
            float p = __cosf(nv + th[c * 256 + j]);
#pragma unroll
            for (int o = 1; o < 32; o <<= 1) {
                float u = __shfl_up_sync(0xffffffffu, p, o);
                if (lane >= o) p *= u;
            }
            if (lane == 31) wt[c][w] = p;
            __syncthreads();
            float pre = 1.f;
            for (int ww = 0; ww < w; ++ww) pre *= wt[c][ww];
            outs[c][off] = p * pre;
        }
    }
}

__global__ void pool_cls_kernel(const float* __restrict__ h, const float* __restrict__ Wc,
                                const float* __restrict__ bc, float* __restrict__ out) {
    __shared__ float pooled[256];
    const int b = blockIdx.x, e = threadIdx.x;
    float s = 0.f;
    for (int tt = 0; tt < 256; ++tt) s += h[((size_t)b * 256 + tt) * 256 + e];
    pooled[e] = s * (1.f/256.f);
    __syncthreads();
    if (e < 4) {
        float a = bc[e];
        for (int i = 0; i < 256; i++) a = fmaf(pooled[i], Wc[i * 4 + e], a);
        out[b * 4 + e] = a;
    }
}

extern "C" void kernel_launch(void* const* d_in, const int* in_sizes, int n_in,
                              void* d_out, int out_size)
{
    const int*   x      = (const int*)  d_in[0];
    const float* tokemb = (const float*)d_in[1];
    const float* lstmW  = (const float*)d_in[2];
    const float* lstmB  = (const float*)d_in[3];
    const float* lstmTh = (const float*)d_in[4];
    const float* ln1g   = (const float*)d_in[5];
    const float* ln1b   = (const float*)d_in[6];
    const float* ln2g   = (const float*)d_in[7];
    const float* ln2b   = (const float*)d_in[8];
    const float* qkvTh  = (const float*)d_in[9];
    const float* combW  = (const float*)d_in[10];
    const float* combB  = (const float*)d_in[11];
    const float* ffnTh  = (const float*)d_in[12];
    const float* lin1W  = (const float*)d_in[13];
    const float* lin1B  = (const float*)d_in[14];
    const float* lin2W  = (const float*)d_in[15];
    const float* lin2B  = (const float*)d_in[16];
    const float* clsW   = (const float*)d_in[17];
    const float* clsB   = (const float*)d_in[18];
    float* out = (float*)d_out;

    float *p_zx,*p_wxp,*p_bth,*p_h,*p_q,*p_k,*p_v,*p_at,*p_ffq,*p_t1,*p_t2;
    cudaGetSymbolAddress((void**)&p_zx,  g_zx);
    cudaGetSymbolAddress((void**)&p_wxp, g_wxp);
    cudaGetSymbolAddress((void**)&p_bth, g_bth);
    cudaGetSymbolAddress((void**)&p_h,   g_h);
    cudaGetSymbolAddress((void**)&p_q,   g_q);
    cudaGetSymbolAddress((void**)&p_k,   g_k);
    cudaGetSymbolAddress((void**)&p_v,   g_v);
    cudaGetSymbolAddress((void**)&p_at,  g_at);
    cudaGetSymbolAddress((void**)&p_ffq, g_ffq);
    cudaGetSymbolAddress((void**)&p_t1,  g_t1);
    cudaGetSymbolAddress((void**)&p_t2,  g_t2);

    cudaFuncSetAttribute(attn_kernel, cudaFuncAttributeMaxDynamicSharedMemorySize, ATTN_SMEM);
    cudaFuncSetAttribute(lstm_kernel, cudaFuncAttributeMaxDynamicSharedMemorySize,
                         LSTM_SMEM_FLOATS * 4);

    pack_kernel<<<1024, 256>>>(lstmW, lstmB, lstmTh);
    gemm_kernel<128, true, false><<<dim3(8, 32), 256>>>(
        nullptr, p_wxp, p_zx, ROWS, 1024, 256, p_bth, x, tokemb);
    lstm_kernel<<<128, 256, LSTM_SMEM_FLOATS * 4>>>(lstmW, p_h);

    // ---- layer 0 ----
    qproj3_kernel<<<ROWS/8, 256>>>(p_h, qkvTh, p_q, p_k, p_v);
    attn_kernel<<<Bb*8, 256, ATTN_SMEM>>>(p_q, p_k, p_v, p_at);
    gemm_kernel<64, false, false><<<dim3(4, 32), 256>>>(
        p_at, combW, p_t2, ROWS, 256, 256, combB, nullptr, nullptr);
    resid_ln_kernel<1><<<ROWS, 256>>>(p_h, p_t2, ln1g, ln1b, ffnTh,
                                      p_ffq, nullptr, nullptr);
    gemm_kernel<128, false, true><<<dim3(8, 32), 256>>>(
        p_ffq, lin1W, p_t1, ROWS, 1024, 256, lin1B, nullptr, nullptr);
    gemm_kernel<64, false, false><<<dim3(4, 32), 256>>>(
        p_t1, lin2W, p_t2, ROWS, 256, 1024, lin2B, nullptr, nullptr);
    resid_ln_kernel<3><<<ROWS, 256>>>(p_h, p_t2, ln2g, ln2b, qkvTh + 3*256,
                                      p_q, p_k, p_v);

    // ---- layer 1 ----
    attn_kernel<<<Bb*8, 256, ATTN_SMEM>>>(p_q, p_k, p_v, p_at);
    gemm_kernel<64, false, false><<<dim3(4, 32), 256>>>(
        p_at, combW + 256*256, p_t2, ROWS, 256, 256, combB + 256, nullptr, nullptr);
    resid_ln_kernel<1><<<ROWS, 256>>>(p_h, p_t2, ln1g + 256, ln1b + 256,
                                      ffnTh + 256, p_ffq, nullptr, nullptr);
    gemm_kernel<128, false, true><<<dim3(8, 32), 256>>>(
        p_ffq, lin1W + 256*1024, p_t1, ROWS, 1024, 256, lin1B + 1024,
        nullptr, nullptr);
    gemm_kernel<64, false, false><<<dim3(4, 32), 256>>>(
        p_t1, lin2W + 1024*256, p_t2, ROWS, 256, 1024, lin2B + 256,
        nullptr, nullptr);
    resid_ln_kernel<0><<<ROWS, 256>>>(p_h, p_t2, ln2g + 256, ln2b + 256,
                                      nullptr, nullptr, nullptr, nullptr);

    pool_cls_kernel<<<Bb, 256>>>(p_h, clsW, clsB, out);
}

// round 17
// speedup vs baseline: 2.2315x; 1.0006x over previous
#include <cuda_runtime.h>
#include <math.h>
#include <cooperative_groups.h>
namespace cg = cooperative_groups;

#define Bb 16
#define Ss 256
#define Ee 256
#define ROWS (Bb*Ss)
#define FFNf 1024

typedef unsigned long long u64;

__device__ float g_zx [ROWS*1024];
__device__ float g_wxp[256*1024];
__device__ float g_bth[1024];
__device__ float g_h  [ROWS*Ee];
__device__ float g_q  [ROWS*Ee];
__device__ float g_k  [ROWS*Ee];
__device__ float g_v  [ROWS*Ee];
__device__ float g_at [ROWS*Ee];
__device__ float g_ffq[ROWS*Ee];
__device__ float g_t1 [ROWS*FFNf];
__device__ float g_t2 [ROWS*Ee];

__device__ __forceinline__ float sigm_poly(float x) {
    float x2 = x * x;
    float p = fmaf(x2, 2.13569388e-5f, -2.10813492e-4f);
    p = fmaf(x2, p, 2.08333333e-3f);
    p = fmaf(x2, p, -2.08333333e-2f);
    p = fmaf(x2, p, 0.25f);
    return fmaf(x, p, 0.5f);
}
__device__ __forceinline__ float tanh_poly(float x) {
    float x2 = x * x;
    float num = x * fmaf(x2, fmaf(x2, 1.f, 105.f), 945.f);
    float den = fmaf(x2, fmaf(x2, 15.f, 420.f), 945.f);
    return __fdividef(num, den);
}
__device__ __forceinline__ float tanh_pade(float x) {
    float x2 = x * x;
    float num = x * fmaf(x2, fmaf(x2, fmaf(x2, 1.f, 378.f), 17325.f), 135135.f);
    float den = fmaf(x2, fmaf(x2, fmaf(x2, 28.f, 3150.f), 62370.f), 135135.f);
    return __fdividef(num, den);
}

// ---- packed fp32x2 helpers (sm_103a FFMA2) ----
__device__ __forceinline__ u64 pk2(float x) {
    u64 r; asm("mov.b64 %0, {%1, %1};" : "=l"(r) : "f"(x)); return r;
}
__device__ __forceinline__ void f2(u64& a, u64 x, u64 y) {
    asm("fma.rn.f32x2 %0, %1, %2, %0;" : "+l"(a) : "l"(x), "l"(y));
}
__device__ __forceinline__ void upk2(u64 v, float& lo, float& hi) {
    asm("mov.b64 {%0, %1}, %2;" : "=f"(lo), "=f"(hi) : "l"(v));
}
__device__ __forceinline__ uint32_t smem_u32(const void* p) {
    uint32_t a;
    asm("{ .reg .u64 t; cvta.to.shared.u64 t, %1; cvt.u32.u64 %0, t; }"
        : "=r"(a) : "l"(p));
    return a;
}
__device__ __forceinline__ void mbar_wait_cluster(uint32_t mbar, uint32_t ph) {
    asm volatile(
        "{\n\t.reg .pred P;\n"
        "LW_%=:\n\t"
        "mbarrier.try_wait.parity.acquire.cluster.shared::cta.b64 P, [%0], %1, 0x989680;\n\t"
        "@P bra.uni LD_%=;\n\t"
        "bra.uni LW_%=;\n"
        "LD_%=:\n\t}"
        :: "r"(mbar), "r"(ph) : "memory");
}

// pack Wx -> [k][g*256+j]; fold b+theta
__global__ void pack_kernel(const float* __restrict__ W, const float* __restrict__ B,
                            const float* __restrict__ Th) {
    int idx = blockIdx.x * 256 + threadIdx.x;
    int k = idx >> 10, n = idx & 1023, g = n >> 8, j = n & 255;
    g_wxp[idx] = W[g * 131072 + k * 256 + j];
    if (idx < 1024) g_bth[idx] = B[idx] + Th[idx];
}

// ---- fp32 GEMM: 128xTN tile, 256 thr, 8x(TN/16) micro, 2 CTAs/SM forced ----
template<int TN, bool GATHER, bool RELU>
__global__ __launch_bounds__(256, 2) void gemm_kernel(
    const float* __restrict__ A, const float* __restrict__ Bm, float* __restrict__ C,
    int M, int N, int K, const float* __restrict__ bias,
    const int* __restrict__ tok, const float* __restrict__ emb)
{
    constexpr int NW = TN / 16;
    constexpr int NP = NW / 2;
    __shared__ float AsT[2][16][136];
    __shared__ float Bs [2][16][136];
    __shared__ int   toks[128];
    const int t = threadIdx.x;
    const int n0 = blockIdx.x * TN, m0 = blockIdx.y << 7;
    const int ar = t >> 1, ac8 = (t & 1) << 3;
    const int bk = t >> 4;
    const int bn = (TN == 128) ? ((t & 15) << 3) : ((t & 15) << 2);
    const int tyo = (t >> 4) << 3, txo = (t & 15) * NW;
    if (GATHER) { if (t < 128) toks[t] = tok[m0 + t]; __syncthreads(); }
    const float* arow = GATHER ? (emb + (size_t)toks[ar] * K)
                               : (A   + (size_t)(m0 + ar) * K);
    const float* brow = Bm + (size_t)bk * N + n0 + bn;

    u64 acc[8][NP];
#pragma unroll
    for (int i = 0; i < 8; i++)
#pragma unroll
        for (int j = 0; j < NP; j++) acc[i][j] = 0ull;

    float4 av0 = *(const float4*)(arow + ac8);
    float4 av1 = *(const float4*)(arow + ac8 + 4);
    float4 bv0 = *(const float4*)(brow);
    float4 bv1;
    if (TN == 128) bv1 = *(const float4*)(brow + 4);

    int s = 0, k0 = 0;
    while (true) {
        AsT[s][ac8+0][ar]=av0.x; AsT[s][ac8+1][ar]=av0.y;
        AsT[s][ac8+2][ar]=av0.z; AsT[s][ac8+3][ar]=av0.w;
        AsT[s][ac8+4][ar]=av1.x; AsT[s][ac8+5][ar]=av1.y;
        AsT[s][ac8+6][ar]=av1.z; AsT[s][ac8+7][ar]=av1.w;
        *(float4*)(&Bs[s][bk][bn]) = bv0;
        if (TN == 128) *(float4*)(&Bs[s][bk][bn+4]) = bv1;
        __syncthreads();
        k0 += 16;
        const bool more = (k0 < K);
        if (more) {
            av0 = *(const float4*)(arow + k0 + ac8);
            av1 = *(const float4*)(arow + k0 + ac8 + 4);
            bv0 = *(const float4*)(brow + (size_t)k0 * N);
            if (TN == 128) bv1 = *(const float4*)(brow + (size_t)k0 * N + 4);
        }
#pragma unroll
        for (int kk = 0; kk < 16; kk++) {
            float4 af0 = *(const float4*)(&AsT[s][kk][tyo]);
            float4 af1 = *(const float4*)(&AsT[s][kk][tyo + 4]);
            u64 a2[8];
            a2[0]=pk2(af0.x); a2[1]=pk2(af0.y); a2[2]=pk2(af0.z); a2[3]=pk2(af0.w);
            a2[4]=pk2(af1.x); a2[5]=pk2(af1.y); a2[6]=pk2(af1.z); a2[7]=pk2(af1.w);
            u64 bp[NP];
            {
                ulonglong2 bb0 = *(const ulonglong2*)(&Bs[s][kk][txo]);
                bp[0] = bb0.x; bp[1] = bb0.y;
                if (TN == 128) {
                    ulonglong2 bb1 = *(const ulonglong2*)(&Bs[s][kk][txo + 4]);
                    bp[2] = bb1.x; bp[3] = bb1.y;
                }
            }
#pragma unroll
            for (int i = 0; i < 8; i++)
#pragma unroll
                for (int j = 0; j < NP; j++) f2(acc[i][j], a2[i], bp[j]);
        }
        if (!more) break;
        s ^= 1;
    }
    float bb[NW];
#pragma unroll
    for (int j = 0; j < NW; j++) bb[j] = bias[n0 + txo + j];
#pragma unroll
    for (int i = 0; i < 8; i++) {
        float ov[NW];
#pragma unroll
        for (int j = 0; j < NP; j++) {
            float lo, hi;
            upk2(acc[i][j], lo, hi);
            ov[2*j]   = lo + bb[2*j];
            ov[2*j+1] = hi + bb[2*j+1];
        }
        if (RELU) {
#pragma unroll
            for (int j = 0; j < NW; j++) ov[j] = fmaxf(ov[j], 0.f);
        }
        float* cp = C + (size_t)(m0 + tyo + i) * N + n0 + txo;
        *(float4*)cp = make_float4(ov[0], ov[1], ov[2], ov[3]);
        if (TN == 128) *(float4*)(cp + 4) = make_float4(ov[4], ov[5], ov[6], ov[7]);
    }
}

// ---------------------------------------------------------------------------
// QLSTM recurrence (r15 proven): cluster of 8, W in registers, scalar st.async
// exchange, polynomial gates, incremental PE rotation. Only change vs r15:
// cross-warp cumprod prefix is a 2-step shuffle scan instead of a serial loop.
// ---------------------------------------------------------------------------
#define LSTM_SMEM_FLOATS (8*132 + 2*8*132 + 256 + 256 + 8 + 8)
__global__ __cluster_dims__(8,1,1) __launch_bounds__(256)
void lstm_kernel(const float* __restrict__ W, float* __restrict__ hseq)
{
    extern __shared__ float sm[];
    float* red  = sm;                          // [8][132]
    float* allq = red + 8*132;                 // [2][8][132]
    float* hx   = allq + 2*8*132;              // [256]
    float* cx   = hx + 256;                    // [256]
    float* wtot = cx + 256;                    // [8]
    u64*   mbar = (u64*)(wtot + 8);            // [2]

    cg::cluster_group cluster = cg::this_cluster();
    const int rank = (int)cluster.block_rank();
    const int g    = rank >> 1, half = rank & 1;
    const int b    = blockIdx.x >> 3;
    const int t    = threadIdx.x;
    const int ks   = t >> 5, jc = t & 31;
    const int lane = t & 31, w = t >> 5;

    const uint32_t allq32 = smem_u32(allq);
    const uint32_t mbar32 = smem_u32(mbar);

    if (t == 0) {
        asm volatile("mbarrier.init.shared.b64 [%0], 1;" :: "r"(mbar32) : "memory");
        asm volatile("mbarrier.init.shared.b64 [%0], 1;" :: "r"(mbar32 + 8) : "memory");
    }

    const float* gW = W + g * 131072 + 65536 + half * 128;
    ulonglong2 wr[32];
#pragma unroll
    for (int kk = 0; kk < 32; kk++)
        wr[kk] = *(const ulonglong2*)(gW + (size_t)((kk << 3) + ks) * 256 + (jc << 2));

    hx[t] = 0.f; cx[t] = 0.f;

    // PE incremental rotation state: (sin, cos)(step * d)
    float ped = __expf((float)((t >> 1) << 1) * (-9.210340371976184f / 256.f));
    float psd = __sinf(ped), pcd = __cosf(ped);
    float ps = 0.f, pc = 1.f;

    uint32_t paq[8], pmb[8];
#pragma unroll
    for (int r = 0; r < 8; r++) {
        asm("mapa.shared::cluster.u32 %0, %1, %2;" : "=r"(paq[r]) : "r"(allq32), "r"(r));
        asm("mapa.shared::cluster.u32 %0, %1, %2;" : "=r"(pmb[r]) : "r"(mbar32), "r"(r));
    }

    __syncthreads();
    cluster.sync();

    const float* zxp = g_zx + (size_t)b * 256 * 1024 + g * 256 + half * 128;
    float zcur = (t < 128) ? zxp[t] : 0.f;

    for (int step = 0; step < 256; ++step) {
        const int par = step & 1;
        u64 acc01 = 0ull, acc23 = 0ull;
#pragma unroll
        for (int kk = 0; kk < 32; ++kk) {
            u64 hv2 = pk2(hx[(kk << 3) + ks]);
            f2(acc01, hv2, wr[kk].x);
            f2(acc23, hv2, wr[kk].y);
        }
        float znext = 0.f;
        if (t < 128) {
            int sn = (step < 255) ? step + 1 : step;
            znext = zxp[(size_t)sn * 1024 + t];
        }
        {
            float a0, a1, a2, a3;
            upk2(acc01, a0, a1); upk2(acc23, a2, a3);
            *(float4*)&red[ks * 132 + (jc << 2)] = make_float4(a0, a1, a2, a3);
        }
        __syncthreads();
        float p = 0.f;
        if (t < 128) {
            float z = red[t] + red[132 + t] + red[264 + t] + red[396 + t]
                    + red[528 + t] + red[660 + t] + red[792 + t] + red[924 + t]
                    + zcur;
            p = __cosf(z);
#pragma unroll
            for (int off = 1; off < 32; off <<= 1) {
                float u = __shfl_up_sync(0xffffffffu, p, off);
                if (lane >= off) p *= u;
            }
            if (lane == 31) wtot[w] = p;
        }
        zcur = znext;
        __syncthreads();
        // cross-warp prefix of wtot[0..3] via shuffle scan (uniform ~40 cyc,
        // replaces the serial per-warp LDS chain)
        float wv = (lane < 4) ? wtot[lane] : 1.f;
        {
            float uu = __shfl_up_sync(0xffffffffu, wv, 1);
            if (lane >= 1 && lane < 4) wv *= uu;
            uu = __shfl_up_sync(0xffffffffu, wv, 2);
            if (lane >= 2 && lane < 4) wv *= uu;
        }
        float pre = (w == 0) ? 1.f : __shfl_sync(0xffffffffu, wv, w - 1);
        if (t == 0) {
            asm volatile("mbarrier.arrive.expect_tx.shared.b64 _, [%0], 4096;"
                         :: "r"(mbar32 + par * 8) : "memory");
        }
        if (t < 128) {
            float sv = p * pre;
            const uint32_t off4 = (uint32_t)(par * 1056 + rank * 132 + t) * 4u;
            const uint32_t svb = __float_as_uint(sv);
#pragma unroll
            for (int r = 0; r < 8; r++) {
                asm volatile(
                    "st.async.shared::cluster.mbarrier::complete_tx::bytes.b32 [%0], %1, [%2];"
                    :: "r"(paq[r] + off4), "r"(svb), "r"(pmb[r] + par * 8) : "memory");
            }
        }
        mbar_wait_cluster(mbar32 + par * 8, (uint32_t)((step >> 1) & 1));
        {
            const int sh = t >> 7, off = t & 127;
            const float* aq = allq + par * 1056;
            float qg4[4];
#pragma unroll
            for (int gg = 0; gg < 4; gg++) {
                float v = aq[(gg * 2 + sh) * 132 + off];
                if (sh) v *= aq[(gg * 2) * 132 + 127];
                qg4[gg] = v;
            }
            float f  = sigm_poly(qg4[0]);
            float ii = sigm_poly(qg4[1]);
            float gg = tanh_poly(qg4[2]);
            float oo = sigm_poly(qg4[3]);
            float cn = f * cx[t] + ii * gg;
            cx[t] = cn;
            float hn = oo * tanh_pade(cn);
            hx[t] = hn;
            if (rank == 0) {
                float pe = (t & 1) ? pc : ps;
                hseq[((size_t)b * 256 + step) * 256 + t] = hn + pe;
            }
            float ns = fmaf(ps, pcd,  pc * psd);
            float nc = fmaf(pc, pcd, -ps * psd);
            ps = ns; pc = nc;
        }
        __syncthreads();
    }
    cluster.sync();
}

// fused q/k/v qproj: one warp per row, reads h once, writes 3 outputs
__global__ void qproj3_kernel(const float* __restrict__ h, const float* __restrict__ th,
                              float* __restrict__ qo, float* __restrict__ ko,
                              float* __restrict__ vo) {
    const int w = threadIdx.x >> 5, lane = threadIdx.x & 31;
    const int row = blockIdx.x * 8 + w;
    const float* hr = h + (size_t)row * 256 + lane * 8;
    float4 h0 = *(const float4*)hr, h1 = *(const float4*)(hr + 4);
    float* outs[3] = {qo, ko, vo};
#pragma unroll
    for (int c = 0; c < 3; c++) {
        const float* tr = th + c * 256 + lane * 8;
        float4 t0 = *(const float4*)tr, t1 = *(const float4*)(tr + 4);
        float p[8], run;
        run  = __cosf(h0.x+t0.x); p[0]=run;  run *= __cosf(h0.y+t0.y); p[1]=run;
        run *= __cosf(h0.z+t0.z); p[2]=run;  run *= __cosf(h0.w+t0.w); p[3]=run;
        run *= __cosf(h1.x+t1.x); p[4]=run;  run *= __cosf(h1.y+t1.y); p[5]=run;
        run *= __cosf(h1.z+t1.z); p[6]=run;  run *= __cosf(h1.w+t1.w); p[7]=run;
        float incl = run;
#pragma unroll
        for (int off = 1; off < 32; off <<= 1) {
            float u = __shfl_up_sync(0xffffffffu, incl, off);
            if (lane >= off) incl *= u;
        }
        float ex = __shfl_up_sync(0xffffffffu, incl, 1);
        if (lane == 0) ex = 1.f;
        float* o = outs[c] + (size_t)row * 256 + lane * 8;
        *(float4*)o     = make_float4(ex*p[0], ex*p[1], ex*p[2], ex*p[3]);
        *(float4*)(o+4) = make_float4(ex*p[4], ex*p[5], ex*p[6], ex*p[7]);
    }
}

// fused attention, 2-row blocking per warp, FFMA2 inner products
#define ATTN_SMEM (36864 + 33280 + 16384 + 2048)
__global__ __launch_bounds__(256) void attn_kernel(const float* __restrict__ Q,
    const float* __restrict__ K, const float* __restrict__ V, float* __restrict__ O)
{
    extern __shared__ float sm[];
    float* kh = sm;               // [256][36]
    float* vt = sm + 256 * 36;    // [32][260]
    float* ps = vt + 32 * 260;    // [8][2][256]
    float* qs = ps + 8 * 512;     // [8][64]
    const int b = blockIdx.x >> 3, hh = blockIdx.x & 7;
    const int t = threadIdx.x, w = t >> 5, lane = t & 31;
    const size_t base = ((size_t)b * 256) * 256 + hh * 32;
    for (int idx = t; idx < 8192; idx += 256) {
        int kr = idx >> 5, d = idx & 31;
        size_t go = base + (size_t)kr * 256 + d;
        kh[kr * 36 + d]  = K[go];
        vt[d * 260 + kr] = V[go];
    }
    __syncthreads();
    float* qsw = qs + w * 64;
    float* ps0 = ps + w * 512;
    float* ps1 = ps0 + 256;
    for (int i = 0; i < 16; i++) {
        const int r0 = w + 8 * i, r1 = r0 + 128;
        qsw[lane]      = Q[base + (size_t)r0 * 256 + lane];
        qsw[32 + lane] = Q[base + (size_t)r1 * 256 + lane];
        __syncwarp();
        u64 qa[16], qb[16];
        {
            const ulonglong2* qp = (const ulonglong2*)qsw;
#pragma unroll
            for (int u = 0; u < 8; u++) {
                ulonglong2 v0 = qp[u];     qa[2*u] = v0.x; qa[2*u+1] = v0.y;
                ulonglong2 v1 = qp[u + 8]; qb[2*u] = v1.x; qb[2*u+1] = v1.y;
            }
        }
        float s0[8], s1[8];
#pragma unroll
        for (int c = 0; c < 8; c++) {
            const ulonglong2* kp = (const ulonglong2*)(kh + (c * 32 + lane) * 36);
            u64 a0 = 0ull, a1 = 0ull;
#pragma unroll
            for (int u = 0; u < 8; u++) {
                ulonglong2 kv = kp[u];
                f2(a0, qa[2*u], kv.x); f2(a0, qa[2*u+1], kv.y);
                f2(a1, qb[2*u], kv.x); f2(a1, qb[2*u+1], kv.y);
            }
            float lo, hi;
            upk2(a0, lo, hi); s0[c] = (lo + hi) * 0.17677669529663689f;
            upk2(a1, lo, hi); s1[c] = (lo + hi) * 0.17677669529663689f;
        }
        float m0 = s0[0], m1 = s1[0];
#pragma unroll
        for (int c = 1; c < 8; c++) { m0 = fmaxf(m0, s0[c]); m1 = fmaxf(m1, s1[c]); }
#pragma unroll
        for (int off = 16; off; off >>= 1) {
            m0 = fmaxf(m0, __shfl_xor_sync(0xffffffffu, m0, off));
            m1 = fmaxf(m1, __shfl_xor_sync(0xffffffffu, m1, off));
        }
        float sum0 = 0.f, sum1 = 0.f;
#pragma unroll
        for (int c = 0; c < 8; c++) {
            s0[c] = __expf(s0[c] - m0); sum0 += s0[c];
            s1[c] = __expf(s1[c] - m1); sum1 += s1[c];
        }
#pragma unroll
        for (int off = 16; off; off >>= 1) {
            sum0 += __shfl_xor_sync(0xffffffffu, sum0, off);
            sum1 += __shfl_xor_sync(0xffffffffu, sum1, off);
        }
#pragma unroll
        for (int c = 0; c < 8; c++) {
            ps0[c * 32 + lane] = s0[c];
            ps1[c * 32 + lane] = s1[c];
        }
        __syncwarp();
        u64 a0 = 0ull, a1 = 0ull;
        const ulonglong2* pp0 = (const ulonglong2*)ps0;
        const ulonglong2* pp1 = (const ulonglong2*)ps1;
        const ulonglong2* vp  = (const ulonglong2*)(vt + lane * 260);
#pragma unroll
        for (int k8 = 0; k8 < 64; k8++) {
            ulonglong2 vv = vp[k8];
            ulonglong2 p0 = pp0[k8];
            ulonglong2 p1 = pp1[k8];
            f2(a0, p0.x, vv.x); f2(a0, p0.y, vv.y);
            f2(a1, p1.x, vv.x); f2(a1, p1.y, vv.y);
        }
        float lo, hi;
        upk2(a0, lo, hi); O[base + (size_t)r0 * 256 + lane] = (lo + hi) / sum0;
        upk2(a1, lo, hi); O[base + (size_t)r1 * 256 + lane] = (lo + hi) / sum1;
        __syncwarp();
    }
}

// residual add + LayerNorm; optionally fused qproj of the LN output (NQ outputs)
template<int NQ>
__global__ void resid_ln_kernel(float* __restrict__ h, const float* __restrict__ d,
                                const float* __restrict__ gw, const float* __restrict__ bw,
                                const float* __restrict__ th,
                                float* __restrict__ q0, float* __restrict__ q1,
                                float* __restrict__ q2) {
    const int row = blockIdx.x, j = threadIdx.x, w = j >> 5, lane = j & 31;
    __shared__ float ssum[8], ssq[8], wt[3][8];
    size_t off = (size_t)row * 256 + j;
    float v = h[off] + d[off];
    float s = v, s2 = v * v;
#pragma unroll
    for (int o = 16; o; o >>= 1) {
        s  += __shfl_xor_sync(0xffffffffu, s, o);
        s2 += __shfl_xor_sync(0xffffffffu, s2, o);
    }
    if (lane == 0) { ssum[w] = s; ssq[w] = s2; }
    __syncthreads();
    if (j == 0) {
        float S = 0.f, S2 = 0.f;
        for (int i = 0; i < 8; i++) { S += ssum[i]; S2 += ssq[i]; }
        ssum[0] = S; ssq[0] = S2;
    }
    __syncthreads();
    float mean = ssum[0] * (1.f/256.f);
    float var  = ssq[0]  * (1.f/256.f) - mean * mean;
    float nv = (v - mean) * rsqrtf(var + 1e-5f) * gw[j] + bw[j];
    h[off] = nv;
    if (NQ > 0) {
        float* outs[3] = {q0, q1, q2};
#pragma unroll
        for (int c = 0; c < NQ; c++) {
            float p = __cosf(nv + th[c * 256 + j]);
#pragma unroll
            for (int o = 1; o < 32; o <<= 1) {
                float u = __shfl_up_sync(0xffffffffu, p, o);
                if (lane >= o) p *= u;
            }
            if (lane == 31) wt[c][w] = p;
            __syncthreads();
            float pre = 1.f;
            for (int ww = 0; ww < w; ++ww) pre *= wt[c][ww];
            outs[c][off] = p * pre;
        }
    }
}

__global__ void pool_cls_kernel(const float* __restrict__ h, const float* __restrict__ Wc,
                                const float* __restrict__ bc, float* __restrict__ out) {
    __shared__ float pooled[256];
    const int b = blockIdx.x, e = threadIdx.x;
    float s = 0.f;
    for (int tt = 0; tt < 256; ++tt) s += h[((size_t)b * 256 + tt) * 256 + e];
    pooled[e] = s * (1.f/256.f);
    __syncthreads();
    if (e < 4) {
        float a = bc[e];
        for (int i = 0; i < 256; i++) a = fmaf(pooled[i], Wc[i * 4 + e], a);
        out[b * 4 + e] = a;
    }
}

extern "C" void kernel_launch(void* const* d_in, const int* in_sizes, int n_in,
                              void* d_out, int out_size)
{
    const int*   x      = (const int*)  d_in[0];
    const float* tokemb = (const float*)d_in[1];
    const float* lstmW  = (const float*)d_in[2];
    const float* lstmB  = (const float*)d_in[3];
    const float* lstmTh = (const float*)d_in[4];
    const float* ln1g   = (const float*)d_in[5];
    const float* ln1b   = (const float*)d_in[6];
    const float* ln2g   = (const float*)d_in[7];
    const float* ln2b   = (const float*)d_in[8];
    const float* qkvTh  = (const float*)d_in[9];
    const float* combW  = (const float*)d_in[10];
    const float* combB  = (const float*)d_in[11];
    const float* ffnTh  = (const float*)d_in[12];
    const float* lin1W  = (const float*)d_in[13];
    const float* lin1B  = (const float*)d_in[14];
    const float* lin2W  = (const float*)d_in[15];
    const float* lin2B  = (const float*)d_in[16];
    const float* clsW   = (const float*)d_in[17];
    const float* clsB   = (const float*)d_in[18];
    float* out = (float*)d_out;

    float *p_zx,*p_wxp,*p_bth,*p_h,*p_q,*p_k,*p_v,*p_at,*p_ffq,*p_t1,*p_t2;
    cudaGetSymbolAddress((void**)&p_zx,  g_zx);
    cudaGetSymbolAddress((void**)&p_wxp, g_wxp);
    cudaGetSymbolAddress((void**)&p_bth, g_bth);
    cudaGetSymbolAddress((void**)&p_h,   g_h);
    cudaGetSymbolAddress((void**)&p_q,   g_q);
    cudaGetSymbolAddress((void**)&p_k,   g_k);
    cudaGetSymbolAddress((void**)&p_v,   g_v);
    cudaGetSymbolAddress((void**)&p_at,  g_at);
    cudaGetSymbolAddress((void**)&p_ffq, g_ffq);
    cudaGetSymbolAddress((void**)&p_t1,  g_t1);
    cudaGetSymbolAddress((void**)&p_t2,  g_t2);

    cudaFuncSetAttribute(attn_kernel, cudaFuncAttributeMaxDynamicSharedMemorySize, ATTN_SMEM);
    cudaFuncSetAttribute(lstm_kernel, cudaFuncAttributeMaxDynamicSharedMemorySize,
                         LSTM_SMEM_FLOATS * 4);

    pack_kernel<<<1024, 256>>>(lstmW, lstmB, lstmTh);
    gemm_kernel<128, true, false><<<dim3(8, 32), 256>>>(
        nullptr, p_wxp, p_zx, ROWS, 1024, 256, p_bth, x, tokemb);
    lstm_kernel<<<128, 256, LSTM_SMEM_FLOATS * 4>>>(lstmW, p_h);

    // ---- layer 0 ----
    qproj3_kernel<<<ROWS/8, 256>>>(p_h, qkvTh, p_q, p_k, p_v);
    attn_kernel<<<Bb*8, 256, ATTN_SMEM>>>(p_q, p_k, p_v, p_at);
    gemm_kernel<64, false, false><<<dim3(4, 32), 256>>>(
        p_at, combW, p_t2, ROWS, 256, 256, combB, nullptr, nullptr);
    resid_ln_kernel<1><<<ROWS, 256>>>(p_h, p_t2, ln1g, ln1b, ffnTh,
                                      p_ffq, nullptr, nullptr);
    gemm_kernel<128, false, true><<<dim3(8, 32), 256>>>(
        p_ffq, lin1W, p_t1, ROWS, 1024, 256, lin1B, nullptr, nullptr);
    gemm_kernel<64, false, false><<<dim3(4, 32), 256>>>(
        p_t1, lin2W, p_t2, ROWS, 256, 1024, lin2B, nullptr, nullptr);
    resid_ln_kernel<3><<<ROWS, 256>>>(p_h, p_t2, ln2g, ln2b, qkvTh + 3*256,
                                      p_q, p_k, p_v);

    // ---- layer 1 ----
    attn_kernel<<<Bb*8, 256, ATTN_SMEM>>>(p_q, p_k, p_v, p_at);
    gemm_kernel<64, false, false><<<dim3(4, 32), 256>>>(
        p_at, combW + 256*256, p_t2, ROWS, 256, 256, combB + 256, nullptr, nullptr);
    resid_ln_kernel<1><<<ROWS, 256>>>(p_h, p_t2, ln1g + 256, ln1b + 256,
                                      ffnTh + 256, p_ffq, nullptr, nullptr);
    gemm_kernel<128, false, true><<<dim3(8, 32), 256>>>(
        p_ffq, lin1W + 256*1024, p_t1, ROWS, 1024, 256, lin1B + 1024,
        nullptr, nullptr);
    gemm_kernel<64, false, false><<<dim3(4, 32), 256>>>(
        p_t1, lin2W + 1024*256, p_t2, ROWS, 256, 1024, lin2B + 256,
        nullptr, nullptr);
    resid_ln_kernel<0><<<ROWS, 256>>>(p_h, p_t2, ln2g + 256, ln2b + 256,
                                      nullptr, nullptr, nullptr, nullptr);

    pool_cls_kernel<<<Bb, 256>>>(p_h, clsW, clsB, out);
}